// round 9
// baseline (speedup 1.0000x reference)
#include <cuda_runtime.h>
#include <math.h>
#include <stdint.h>

#define NMAX 50000
#define EMAX 500000

// ---------------- static scratch ------------------------------------------
__device__ float g_XN[NMAX * 128];
__device__ float g_Q[NMAX * 128];
__device__ float g_K[NMAX * 128];
__device__ float g_V[NMAX * 128];
__device__ float g_AGG[NMAX * 128];
__device__ float g_XMID[NMAX * 128];
__device__ float g_FFNH[NMAX * 256];
__device__ float g_HE[EMAX * 64];
__device__ float g_LOG[EMAX * 8];
__device__ float g_ATT[EMAX * 8];
__device__ float g_WS[EMAX * 128];
__device__ int   g_perm[EMAX];
__device__ int   g_srcs[EMAX];
__device__ int   g_dsts[EMAX];
__device__ int   g_cnt[NMAX];
__device__ int   g_rowstart[NMAX + 1];
__device__ int   g_cursor[NMAX];
__device__ int   g_bsum[256];
__device__ int   g_bsumex[256];

__device__ __forceinline__ float gelu_f(float x) {
    return 0.5f * x * (1.0f + erff(x * 0.70710678118654752f));
}
__device__ __forceinline__ float sigmoid_f(float x) {
    return 1.0f / (1.0f + expf(-x));
}

__device__ __forceinline__ void cpa16(uint32_t dst, const void* src, bool valid) {
    int sz = valid ? 16 : 0;
    asm volatile("cp.async.cg.shared.global [%0], [%1], 16, %2;"
                 :: "r"(dst), "l"(src), "r"(sz) : "memory");
}
#define CP_COMMIT() asm volatile("cp.async.commit_group;" ::: "memory")
template <int Ng>
__device__ __forceinline__ void cp_wait() {
    asm volatile("cp.async.wait_group %0;" :: "n"(Ng) : "memory");
}

__device__ __forceinline__ void mma_tf32(float* c, const unsigned* a, const unsigned* b) {
    asm volatile(
        "mma.sync.aligned.m16n8k8.row.col.f32.tf32.tf32.f32 "
        "{%0,%1,%2,%3}, {%4,%5,%6,%7}, {%8,%9}, {%0,%1,%2,%3};"
        : "+f"(c[0]), "+f"(c[1]), "+f"(c[2]), "+f"(c[3])
        : "r"(a[0]), "r"(a[1]), "r"(a[2]), "r"(a[3]), "r"(b[0]), "r"(b[1]));
}
__device__ __forceinline__ void ldsm_x4(unsigned* a, uint32_t addr) {
    asm volatile("ldmatrix.sync.aligned.m8n8.x4.shared.b16 {%0,%1,%2,%3}, [%4];"
                 : "=r"(a[0]), "=r"(a[1]), "=r"(a[2]), "=r"(a[3]) : "r"(addr));
}

// ---------------- tf32 mma GEMM v3: 3-stage cp.async + ldmatrix A -----------
// 128 rows x BN cols per CTA, BK=32, 8 warps.
// modes: 0:+bias 1:gelu 2:res+ 3:res+gam*+bet 4:sigmoid*att*V[src]
template <int BN>
__global__ void __launch_bounds__(256, 2) mma3(
        const float* __restrict__ A, const float* __restrict__ W,
        const float* __restrict__ bias, const float* __restrict__ res,
        const float* __restrict__ gam, const float* __restrict__ bet,
        const float* __restrict__ V, const int* __restrict__ srcs,
        const float* __restrict__ ATT,
        float* __restrict__ C, int M, int N, int K, int mode,
        const int* __restrict__ rowidx) {
    constexpr int NF = BN / 32;
    constexpr int WN = BN / 4;
    constexpr int ASTR = 36;                 // A smem row stride (floats); 144B = 9*16
    constexpr int BSTR = BN + 4;
    constexpr int ASZ = 128 * ASTR;
    constexpr int BSZ = 32 * BSTR;
    constexpr int STG = ASZ + BSZ;           // floats per stage
    constexpr int BCH = (32 * (BN / 4)) / 256;
    extern __shared__ float dsm[];
    const uint32_t smBase = (uint32_t)__cvta_generic_to_shared(dsm);
    const int tid = threadIdx.x, lane = tid & 31, wid = tid >> 5;
    const int wm = wid & 1, wn = wid >> 1;
    const int row0 = blockIdx.y * 128, col0 = blockIdx.x * BN;
    const int warpM = wm * 64, warpN = wn * WN;
    // ldmatrix per-lane row offset (bytes): group g = lane>>3, rl = lane&7
    const int g = lane >> 3, rl = lane & 7;
    const uint32_t aLaneOff = (uint32_t)(((rl + (g & 1) * 8) * ASTR + (g >> 1) * 4) * 4);

    float acc[4][NF][4];
    #pragma unroll
    for (int i = 0; i < 4; i++)
        #pragma unroll
        for (int j = 0; j < NF; j++) {
            acc[i][j][0] = 0.f; acc[i][j][1] = 0.f; acc[i][j][2] = 0.f; acc[i][j][3] = 0.f;
        }

    const int ntiles = K >> 5;

    auto load_tile = [&](int stage, int t) {
        const int kt = t << 5;
        uint32_t ab = smBase + (uint32_t)(stage * STG) * 4;
        #pragma unroll
        for (int it = 0; it < 4; it++) {
            int cI = tid + it * 256;
            int r = cI >> 3, q = cI & 7;
            int gr = row0 + r;
            bool v = gr < M;
            const float* src = A;
            if (v) {
                int pr = rowidx ? rowidx[gr] : gr;
                src = A + (size_t)pr * K + kt + q * 4;
            }
            cpa16(ab + (uint32_t)(r * ASTR + q * 4) * 4, src, v);
        }
        uint32_t bb = smBase + (uint32_t)(stage * STG + ASZ) * 4;
        #pragma unroll
        for (int it = 0; it < BCH; it++) {
            int cI = tid + it * 256;
            int kr = cI / (BN / 4), q = cI % (BN / 4);
            cpa16(bb + (uint32_t)(kr * BSTR + q * 4) * 4,
                  W + (size_t)(kt + kr) * N + col0 + q * 4, true);
        }
    };

    load_tile(0, 0);
    CP_COMMIT();
    if (ntiles > 1) { load_tile(1, 1); CP_COMMIT(); }

    for (int t = 0; t < ntiles; t++) {
        const int cur = t % 3;
        if (t + 1 < ntiles) cp_wait<1>(); else cp_wait<0>();
        __syncthreads();
        if (t + 2 < ntiles) { load_tile((t + 2) % 3, t + 2); CP_COMMIT(); }
        const uint32_t aWarp = smBase + (uint32_t)(cur * STG) * 4 +
                               (uint32_t)(warpM * ASTR) * 4 + aLaneOff;
        const float* Bb = dsm + cur * STG + ASZ;
        #pragma unroll
        for (int ks = 0; ks < 4; ks++) {
            const int k = ks * 8 + (lane & 3);
            unsigned af[4][4];
            #pragma unroll
            for (int mf = 0; mf < 4; mf++)
                ldsm_x4(af[mf], aWarp + (uint32_t)(mf * 16 * ASTR * 4 + ks * 32));
            unsigned bf[NF][2];
            #pragma unroll
            for (int nf = 0; nf < NF; nf++) {
                int n0 = warpN + nf * 8 + (lane >> 2);
                bf[nf][0] = __float_as_uint(Bb[k * BSTR + n0]);
                bf[nf][1] = __float_as_uint(Bb[(k + 4) * BSTR + n0]);
            }
            #pragma unroll
            for (int mf = 0; mf < 4; mf++)
                #pragma unroll
                for (int nf = 0; nf < NF; nf++)
                    mma_tf32(acc[mf][nf], af[mf], bf[nf]);
        }
    }

    // epilogue
    #pragma unroll
    for (int mf = 0; mf < 4; mf++) {
        #pragma unroll
        for (int half = 0; half < 2; half++) {
            int r = row0 + warpM + mf * 16 + (lane >> 2) + half * 8;
            if (r >= M) continue;
            int sn = 0;
            if (mode == 4) sn = srcs[r];
            #pragma unroll
            for (int nf = 0; nf < NF; nf++) {
                int cc = col0 + warpN + nf * 8 + ((lane & 3) << 1);
                float v0 = acc[mf][nf][half * 2 + 0];
                float v1 = acc[mf][nf][half * 2 + 1];
                if (bias) { v0 += bias[cc]; v1 += bias[cc + 1]; }
                size_t idx = (size_t)r * N + cc;
                if (mode == 1) {
                    v0 = gelu_f(v0); v1 = gelu_f(v1);
                } else if (mode == 2) {
                    v0 += res[idx]; v1 += res[idx + 1];
                } else if (mode == 3) {
                    v0 = res[idx] + gam[idx] * v0 + bet[idx];
                    v1 = res[idx + 1] + gam[idx + 1] * v1 + bet[idx + 1];
                } else if (mode == 4) {
                    float at = __ldg(ATT + (size_t)r * 8 + (cc >> 4));
                    v0 = sigmoid_f(v0) * at * __ldg(V + (size_t)sn * 128 + cc);
                    v1 = sigmoid_f(v1) * at * __ldg(V + (size_t)sn * 128 + cc + 1);
                }
                *(float2*)(C + idx) = make_float2(v0, v1);
            }
        }
    }
}

// ---------------- LayerNorm -------------------------------------------------
__global__ void ln_kernel(const float* __restrict__ X, const float* __restrict__ G,
                          const float* __restrict__ B, float* __restrict__ O, int Nrows) {
    int warp = (blockIdx.x * blockDim.x + threadIdx.x) >> 5;
    int lane = threadIdx.x & 31;
    if (warp >= Nrows) return;
    const float* xp = X + (size_t)warp * 128;
    float4 v = *(const float4*)(xp + lane * 4);
    float s = v.x + v.y + v.z + v.w;
    #pragma unroll
    for (int o = 16; o; o >>= 1) s += __shfl_xor_sync(0xffffffffu, s, o);
    float mean = s * (1.0f / 128.0f);
    float d0 = v.x - mean, d1 = v.y - mean, d2 = v.z - mean, d3 = v.w - mean;
    float ss = d0 * d0 + d1 * d1 + d2 * d2 + d3 * d3;
    #pragma unroll
    for (int o = 16; o; o >>= 1) ss += __shfl_xor_sync(0xffffffffu, ss, o);
    float inv = rsqrtf(ss * (1.0f / 128.0f) + 1e-5f);
    float* op = O + (size_t)warp * 128;
    int c = lane * 4;
    op[c + 0] = d0 * inv * G[c + 0] + B[c + 0];
    op[c + 1] = d1 * inv * G[c + 1] + B[c + 1];
    op[c + 2] = d2 * inv * G[c + 2] + B[c + 2];
    op[c + 3] = d3 * inv * G[c + 3] + B[c + 3];
}

// ---------------- counting sort of edges by dst -----------------------------
__global__ void hist_kernel(const int* __restrict__ EI, int* __restrict__ cnt, int E) {
    int e = blockIdx.x * 256 + threadIdx.x;
    if (e < E) atomicAdd(&cnt[EI[E + e]], 1);
}
__global__ void scan1_kernel(const int* __restrict__ cnt, int* __restrict__ excl,
                             int* __restrict__ bsum, int N) {
    __shared__ int sm[256];
    int t = threadIdx.x, i = blockIdx.x * 256 + t;
    int v = (i < N) ? cnt[i] : 0;
    sm[t] = v; __syncthreads();
    for (int o = 1; o < 256; o <<= 1) {
        int a = (t >= o) ? sm[t - o] : 0;
        __syncthreads();
        sm[t] += a;
        __syncthreads();
    }
    if (i < N) excl[i] = sm[t] - v;
    if (t == 255) bsum[blockIdx.x] = sm[255];
}
__global__ void scan2_kernel(const int* __restrict__ bsum, int* __restrict__ bsumex, int nb) {
    __shared__ int sm[256];
    int t = threadIdx.x;
    int v = (t < nb) ? bsum[t] : 0;
    sm[t] = v; __syncthreads();
    for (int o = 1; o < 256; o <<= 1) {
        int a = (t >= o) ? sm[t - o] : 0;
        __syncthreads();
        sm[t] += a;
        __syncthreads();
    }
    bsumex[t] = sm[t] - v;
}
__global__ void scan3_kernel(int* __restrict__ rowstart, int* __restrict__ cursor,
                             const int* __restrict__ bsumex, int N, int E) {
    int i = blockIdx.x * 256 + threadIdx.x;
    if (i < N) {
        int v = rowstart[i] + bsumex[blockIdx.x];
        rowstart[i] = v;
        cursor[i] = v;
        if (i == N - 1) rowstart[N] = E;
    }
}
__global__ void scatter_kernel(const int* __restrict__ EI, int* __restrict__ cursor,
                               int* __restrict__ perm, int* __restrict__ srcs,
                               int* __restrict__ dsts, int E) {
    int e = blockIdx.x * 256 + threadIdx.x;
    if (e >= E) return;
    int d = EI[E + e];
    int pos = atomicAdd(&cursor[d], 1);
    perm[pos] = e;
    srcs[pos] = EI[e];
    dsts[pos] = d;
}

// ---------------- logits (sorted order), fused ea-MLP -----------------------
__global__ void logits_kernel(const float* __restrict__ EA, const int* __restrict__ perm,
                              const int* __restrict__ srcs, const int* __restrict__ dsts,
                              const float* __restrict__ W1, const float* __restrict__ B1,
                              const float* __restrict__ W2, const float* __restrict__ B2,
                              const float* __restrict__ Q, const float* __restrict__ Kk,
                              float* __restrict__ LOG, int E) {
    __shared__ float attr[64][33];
    __shared__ float w1s[32][65];
    __shared__ float ha[64][65];
    __shared__ float w2s[64][9];
    __shared__ float b2s[8];
    __shared__ int s_src[64], s_dst[64], s_perm[64];
    const int tid = threadIdx.x;
    const int e0 = blockIdx.x * 64;
    if (tid < 64) {
        int ge = e0 + tid;
        bool ok = ge < E;
        s_perm[tid] = ok ? perm[ge] : 0;
        s_src[tid] = ok ? srcs[ge] : 0;
        s_dst[tid] = ok ? dsts[ge] : 0;
    }
    for (int i = tid; i < 32 * 64; i += 256) w1s[i >> 6][i & 63] = W1[i];
    for (int i = tid; i < 64 * 8; i += 256) w2s[i >> 3][i & 7] = W2[i];
    if (tid < 8) b2s[tid] = B2[tid];
    __syncthreads();
    for (int i = tid; i < 64 * 32; i += 256) {
        int e = i >> 5, f = i & 31;
        attr[e][f] = (e0 + e < E) ? EA[(size_t)s_perm[e] * 32 + f] : 0.0f;
    }
    __syncthreads();
    {
        const int tx = tid & 15, ty = tid >> 4;
        float acc[4][4] = {};
        for (int k = 0; k < 32; k++) {
            float a[4], b[4];
            #pragma unroll
            for (int i = 0; i < 4; i++) a[i] = attr[(ty << 2) + i][k];
            #pragma unroll
            for (int j = 0; j < 4; j++) b[j] = w1s[k][(tx << 2) + j];
            #pragma unroll
            for (int i = 0; i < 4; i++)
                #pragma unroll
                for (int j = 0; j < 4; j++) acc[i][j] = fmaf(a[i], b[j], acc[i][j]);
        }
        #pragma unroll
        for (int i = 0; i < 4; i++)
            #pragma unroll
            for (int j = 0; j < 4; j++)
                ha[(ty << 2) + i][(tx << 2) + j] =
                    gelu_f(acc[i][j] + __ldg(B1 + (tx << 2) + j));
    }
    __syncthreads();
    for (int i = tid; i < 512; i += 256) {
        int e = i >> 3, h = i & 7;
        int ge = e0 + e;
        if (ge >= E) continue;
        const float* qp = Q + (size_t)s_dst[e] * 128 + h * 16;
        const float* kp = Kk + (size_t)s_src[e] * 128 + h * 16;
        float lg = 0.0f;
        #pragma unroll
        for (int d = 0; d < 16; d += 4) {
            float4 qv = *(const float4*)(qp + d);
            float4 kv = *(const float4*)(kp + d);
            lg += qv.x * kv.x + qv.y * kv.y + qv.z * kv.z + qv.w * kv.w;
        }
        lg *= 0.25f;
        float a = b2s[h];
        #pragma unroll 8
        for (int k = 0; k < 64; k++) a = fmaf(ha[e][k], w2s[k][h], a);
        LOG[(size_t)ge * 8 + h] = lg + a;
    }
}

// ---------------- per-node softmax ------------------------------------------
__global__ void softmax_kernel(const float* __restrict__ LOG, const int* __restrict__ rowstart,
                               float* __restrict__ ATT, int N) {
    int warp = (blockIdx.x * blockDim.x + threadIdx.x) >> 5;
    int lane = threadIdx.x & 31;
    if (warp >= N) return;
    int s0 = rowstart[warp], s1 = rowstart[warp + 1];
    int eo = lane >> 3, h = lane & 7;
    float m = 0.0f;
    for (int i = s0 + eo; i < s1; i += 4) m = fmaxf(m, LOG[(size_t)i * 8 + h]);
    m = fmaxf(m, __shfl_xor_sync(0xffffffffu, m, 8));
    m = fmaxf(m, __shfl_xor_sync(0xffffffffu, m, 16));
    float s = 0.0f;
    for (int i = s0 + eo; i < s1; i += 4) s += expf(LOG[(size_t)i * 8 + h] - m);
    s += __shfl_xor_sync(0xffffffffu, s, 8);
    s += __shfl_xor_sync(0xffffffffu, s, 16);
    float inv = 1.0f / (s + 1e-10f);
    for (int i = s0 + eo; i < s1; i += 4)
        ATT[(size_t)i * 8 + h] = expf(LOG[(size_t)i * 8 + h] - m) * inv;
}

// ---------------- contiguous segment sum ------------------------------------
__global__ void segsum_kernel(const float* __restrict__ WS, const int* __restrict__ rowstart,
                              float* __restrict__ AGG, int N) {
    int warp = (blockIdx.x * blockDim.x + threadIdx.x) >> 5;
    int lane = threadIdx.x & 31;
    if (warp >= N) return;
    int s0 = rowstart[warp], s1 = rowstart[warp + 1];
    float4 acc = make_float4(0.f, 0.f, 0.f, 0.f);
    for (int i = s0; i < s1; i++) {
        float4 v = *(const float4*)(WS + (size_t)i * 128 + lane * 4);
        acc.x += v.x; acc.y += v.y; acc.z += v.z; acc.w += v.w;
    }
    *(float4*)(AGG + (size_t)warp * 128 + lane * 4) = acc;
}

// ---------------- launch ----------------------------------------------------
extern "C" void kernel_launch(void* const* d_in, const int* in_sizes, int n_in,
                              void* d_out, int out_size) {
    const float* x      = (const float*)d_in[0];
    const float* ea     = (const float*)d_in[1];
    const float* gamma  = (const float*)d_in[2];
    const float* beta   = (const float*)d_in[3];
    const float* Wq     = (const float*)d_in[4];
    const float* Wk     = (const float*)d_in[5];
    const float* Wv     = (const float*)d_in[6];
    const float* Wo     = (const float*)d_in[7];
    const float* bo     = (const float*)d_in[8];
    const float* ea_w1  = (const float*)d_in[9];
    const float* ea_b1  = (const float*)d_in[10];
    const float* ea_w2  = (const float*)d_in[11];
    const float* ea_b2  = (const float*)d_in[12];
    const float* eg_w1  = (const float*)d_in[13];
    const float* eg_b1  = (const float*)d_in[14];
    const float* eg_w2  = (const float*)d_in[15];
    const float* eg_b2  = (const float*)d_in[16];
    const float* ln1_g  = (const float*)d_in[17];
    const float* ln1_b  = (const float*)d_in[18];
    const float* ln2_g  = (const float*)d_in[19];
    const float* ln2_b  = (const float*)d_in[20];
    const float* ffn_w1 = (const float*)d_in[21];
    const float* ffn_b1 = (const float*)d_in[22];
    const float* ffn_w2 = (const float*)d_in[23];
    const float* ffn_b2 = (const float*)d_in[24];
    const int*   ei     = (const int*)d_in[25];

    int N = in_sizes[0] / 128;
    int E = in_sizes[25] / 2;

    float *pXN, *pQ, *pK, *pV, *pAGG, *pXMID, *pFFNH, *pHE, *pLOG, *pATT, *pWS;
    int *pPerm, *pSrc, *pDst, *pCnt, *pRow, *pCur, *pBsum, *pBsumex;
    cudaGetSymbolAddress((void**)&pXN, g_XN);
    cudaGetSymbolAddress((void**)&pQ, g_Q);
    cudaGetSymbolAddress((void**)&pK, g_K);
    cudaGetSymbolAddress((void**)&pV, g_V);
    cudaGetSymbolAddress((void**)&pAGG, g_AGG);
    cudaGetSymbolAddress((void**)&pXMID, g_XMID);
    cudaGetSymbolAddress((void**)&pFFNH, g_FFNH);
    cudaGetSymbolAddress((void**)&pHE, g_HE);
    cudaGetSymbolAddress((void**)&pLOG, g_LOG);
    cudaGetSymbolAddress((void**)&pATT, g_ATT);
    cudaGetSymbolAddress((void**)&pWS, g_WS);
    cudaGetSymbolAddress((void**)&pPerm, g_perm);
    cudaGetSymbolAddress((void**)&pSrc, g_srcs);
    cudaGetSymbolAddress((void**)&pDst, g_dsts);
    cudaGetSymbolAddress((void**)&pCnt, g_cnt);
    cudaGetSymbolAddress((void**)&pRow, g_rowstart);
    cudaGetSymbolAddress((void**)&pCur, g_cursor);
    cudaGetSymbolAddress((void**)&pBsum, g_bsum);
    cudaGetSymbolAddress((void**)&pBsumex, g_bsumex);

    // dyn smem: 3 stages of (A 128x36 + B 32x(BN+4)) floats
    const int smem128 = 3 * (128 * 36 + 32 * 132) * 4;   // 105984
    const int smem64  = 3 * (128 * 36 + 32 * 68) * 4;    // 81408
    cudaFuncSetAttribute(mma3<128>, cudaFuncAttributeMaxDynamicSharedMemorySize, smem128);
    cudaFuncSetAttribute(mma3<64>, cudaFuncAttributeMaxDynamicSharedMemorySize, smem64);

    int nb = (N + 255) / 256;
    int lnBlocks = (N * 32 + 255) / 256;
    dim3 gn(1, (N + 127) / 128);
    dim3 ge(1, (E + 127) / 128);

    // order so ncu -s 5 captures mma3 (V projection)
    cudaMemsetAsync(pCnt, 0, (size_t)N * sizeof(int));                       // 1
    ln_kernel<<<lnBlocks, 256>>>(x, ln1_g, ln1_b, pXN, N);                   // 2
    mma3<128><<<gn, 256, smem128>>>(pXN, Wq, nullptr, nullptr, nullptr, nullptr,
        nullptr, nullptr, nullptr, pQ, N, 128, 128, 0, nullptr);             // 3
    mma3<128><<<gn, 256, smem128>>>(pXN, Wk, nullptr, nullptr, nullptr, nullptr,
        nullptr, nullptr, nullptr, pK, N, 128, 128, 0, nullptr);             // 4
    mma3<128><<<gn, 256, smem128>>>(pXN, Wv, nullptr, nullptr, nullptr, nullptr,
        nullptr, nullptr, nullptr, pV, N, 128, 128, 0, nullptr);             // 5 <- profiled
    hist_kernel<<<(E + 255) / 256, 256>>>(ei, pCnt, E);
    scan1_kernel<<<nb, 256>>>(pCnt, pRow, pBsum, N);
    scan2_kernel<<<1, 256>>>(pBsum, pBsumex, nb);
    scan3_kernel<<<nb, 256>>>(pRow, pCur, pBsumex, N, E);
    scatter_kernel<<<(E + 255) / 256, 256>>>(ei, pCur, pPerm, pSrc, pDst, E);

    logits_kernel<<<(E + 63) / 64, 256>>>(ea, pPerm, pSrc, pDst, ea_w1, ea_b1, ea_w2, ea_b2,
                                          pQ, pK, pLOG, E);
    softmax_kernel<<<(N * 32 + 255) / 256, 256>>>(pLOG, pRow, pATT, N);
    // HG = gelu(EA[perm] @ eg_w1 + b1)   [E, 64], K=32
    mma3<64><<<ge, 256, smem64>>>(ea, eg_w1, eg_b1, nullptr, nullptr, nullptr,
        nullptr, nullptr, nullptr, pHE, E, 64, 32, 1, pPerm);
    // WS = sigmoid(HG @ eg_w2 + b2) * att * V[src]   [E, 128], K=64
    mma3<128><<<ge, 256, smem128>>>(pHE, eg_w2, eg_b2, nullptr, nullptr, nullptr,
        pV, pSrc, pATT, pWS, E, 128, 64, 4, nullptr);
    segsum_kernel<<<(N * 32 + 255) / 256, 256>>>(pWS, pRow, pAGG, N);

    mma3<128><<<gn, 256, smem128>>>(pAGG, Wo, bo, x, gamma, beta,
        nullptr, nullptr, nullptr, pXMID, N, 128, 128, 3, nullptr);
    ln_kernel<<<lnBlocks, 256>>>(pXMID, ln2_g, ln2_b, pXN, N);
    dim3 gn2(2, (N + 127) / 128);
    mma3<128><<<gn2, 256, smem128>>>(pXN, ffn_w1, ffn_b1, nullptr, nullptr, nullptr,
        nullptr, nullptr, nullptr, pFFNH, N, 256, 128, 1, nullptr);
    mma3<128><<<gn, 256, smem128>>>(pFFNH, ffn_w2, ffn_b2, pXMID, nullptr, nullptr,
        nullptr, nullptr, nullptr, (float*)d_out, N, 128, 256, 2, nullptr);
}

// round 10
// speedup vs baseline: 1.1601x; 1.1601x over previous
#include <cuda_runtime.h>
#include <math.h>
#include <stdint.h>

#define NMAX 50000
#define EMAX 500000

// ---------------- static scratch ------------------------------------------
__device__ float g_XN[NMAX * 128];
__device__ float g_Q[NMAX * 128];
__device__ float g_K[NMAX * 128];
__device__ float g_V[NMAX * 128];
__device__ float g_AGG[NMAX * 128];
__device__ float g_XMID[NMAX * 128];
__device__ float g_FFNH[NMAX * 256];
__device__ float g_HE[EMAX * 64];
__device__ float g_LOG[EMAX * 8];
__device__ float g_ATT[EMAX * 8];
__device__ int   g_perm[EMAX];
__device__ int   g_srcs[EMAX];
__device__ int   g_dsts[EMAX];
__device__ int   g_cnt[NMAX];
__device__ int   g_rowstart[NMAX + 1];
__device__ int   g_cursor[NMAX];
__device__ int   g_bsum[256];
__device__ int   g_bsumex[256];

__device__ __forceinline__ float gelu_f(float x) {
    return 0.5f * x * (1.0f + erff(x * 0.70710678118654752f));
}
__device__ __forceinline__ float sigmoid_f(float x) {
    return 1.0f / (1.0f + expf(-x));
}

__device__ __forceinline__ void cpa16(uint32_t dst, const void* src, bool valid) {
    int sz = valid ? 16 : 0;
    asm volatile("cp.async.cg.shared.global [%0], [%1], 16, %2;"
                 :: "r"(dst), "l"(src), "r"(sz) : "memory");
}
#define CP_COMMIT() asm volatile("cp.async.commit_group;" ::: "memory")
template <int Ng>
__device__ __forceinline__ void cp_wait() {
    asm volatile("cp.async.wait_group %0;" :: "n"(Ng) : "memory");
}

__device__ __forceinline__ void mma_tf32(float* c, const unsigned* a, const unsigned* b) {
    asm volatile(
        "mma.sync.aligned.m16n8k8.row.col.f32.tf32.tf32.f32 "
        "{%0,%1,%2,%3}, {%4,%5,%6,%7}, {%8,%9}, {%0,%1,%2,%3};"
        : "+f"(c[0]), "+f"(c[1]), "+f"(c[2]), "+f"(c[3])
        : "r"(a[0]), "r"(a[1]), "r"(a[2]), "r"(a[3]), "r"(b[0]), "r"(b[1]));
}

// ---------------- tf32 mma GEMM (R8 winner) + mode-5 fused segment-reduce ---
// 128 rows x BN cols per CTA, BK=32, 8 warps, 2-stage cp.async.
// modes: 0:+bias 1:gelu 2:res+ 3:res+gam*+bet
//        5: gate+reduce: v=sigmoid(+bias)*ATT*V[srcs[row]]; rows are dst-sorted
//           edges; CTA reduces consecutive equal-dst rows in smem and
//           atomicAdds per-segment sums into C (=AGG, zero-initialized).
template <int BN>
__global__ void __launch_bounds__(256, 2) mma2(
        const float* __restrict__ A, const float* __restrict__ W,
        const float* __restrict__ bias, const float* __restrict__ res,
        const float* __restrict__ gam, const float* __restrict__ bet,
        const float* __restrict__ V, const int* __restrict__ srcs,
        const int* __restrict__ dsts, const float* __restrict__ ATT,
        float* __restrict__ C, int M, int N, int K, int mode,
        const int* __restrict__ rowidx) {
    constexpr int NF = BN / 32;
    constexpr int WN = BN / 4;
    constexpr int ASTR = 36;
    constexpr int BSTR = BN + 4;
    constexpr int ASZ = 128 * ASTR;
    constexpr int BSZ = 32 * BSTR;
    constexpr int BCH = (32 * (BN / 4)) / 256;
    extern __shared__ float dsm[];
    float* Abuf = dsm;
    float* Bbuf = dsm + 2 * ASZ;
    const uint32_t aAddr = (uint32_t)__cvta_generic_to_shared(Abuf);
    const uint32_t bAddr = (uint32_t)__cvta_generic_to_shared(Bbuf);
    const int tid = threadIdx.x, lane = tid & 31, wid = tid >> 5;
    const int wm = wid & 1, wn = wid >> 1;
    const int row0 = blockIdx.y * 128, col0 = blockIdx.x * BN;
    const int warpM = wm * 64, warpN = wn * WN;
    float acc[4][NF][4];
    #pragma unroll
    for (int i = 0; i < 4; i++)
        #pragma unroll
        for (int j = 0; j < NF; j++) {
            acc[i][j][0] = 0.f; acc[i][j][1] = 0.f; acc[i][j][2] = 0.f; acc[i][j][3] = 0.f;
        }

    const int ntiles = K >> 5;

    auto load_tile = [&](int stage, int t) {
        const int kt = t << 5;
        uint32_t ab = aAddr + stage * (ASZ * 4);
        #pragma unroll
        for (int it = 0; it < 4; it++) {
            int cI = tid + it * 256;
            int r = cI >> 3, q = cI & 7;
            int gr = row0 + r;
            bool v = gr < M;
            const float* src = A;
            if (v) {
                int pr = rowidx ? rowidx[gr] : gr;
                src = A + (size_t)pr * K + kt + q * 4;
            }
            cpa16(ab + (uint32_t)(r * ASTR + q * 4) * 4, src, v);
        }
        uint32_t bb = bAddr + stage * (BSZ * 4);
        #pragma unroll
        for (int it = 0; it < BCH; it++) {
            int cI = tid + it * 256;
            int kr = cI / (BN / 4), q = cI % (BN / 4);
            cpa16(bb + (uint32_t)(kr * BSTR + q * 4) * 4,
                  W + (size_t)(kt + kr) * N + col0 + q * 4, true);
        }
    };

    load_tile(0, 0);
    CP_COMMIT();
    for (int t = 0; t < ntiles; t++) {
        int cur = t & 1;
        if (t + 1 < ntiles) {
            load_tile(1 - cur, t + 1);
            CP_COMMIT();
            cp_wait<1>();
        } else {
            cp_wait<0>();
        }
        __syncthreads();
        const float* Ab = Abuf + cur * ASZ;
        const float* Bb = Bbuf + cur * BSZ;
        #pragma unroll
        for (int ks = 0; ks < 4; ks++) {
            int k = ks * 8 + (lane & 3);
            unsigned af[4][4];
            #pragma unroll
            for (int mf = 0; mf < 4; mf++) {
                int r = warpM + mf * 16 + (lane >> 2);
                af[mf][0] = __float_as_uint(Ab[r * ASTR + k]);
                af[mf][1] = __float_as_uint(Ab[(r + 8) * ASTR + k]);
                af[mf][2] = __float_as_uint(Ab[r * ASTR + k + 4]);
                af[mf][3] = __float_as_uint(Ab[(r + 8) * ASTR + k + 4]);
            }
            unsigned bf[NF][2];
            #pragma unroll
            for (int nf = 0; nf < NF; nf++) {
                int n0 = warpN + nf * 8 + (lane >> 2);
                bf[nf][0] = __float_as_uint(Bb[k * BSTR + n0]);
                bf[nf][1] = __float_as_uint(Bb[(k + 4) * BSTR + n0]);
            }
            #pragma unroll
            for (int mf = 0; mf < 4; mf++)
                #pragma unroll
                for (int nf = 0; nf < NF; nf++)
                    mma_tf32(acc[mf][nf], af[mf], bf[nf]);
        }
        __syncthreads();
    }

    if (mode == 5) {
        // ---- fused gate epilogue + per-dst segment reduction ----
        constexpr int TSTR = 132;
        float* tile = dsm;                       // 128 x 132 floats (reuse pipeline smem)
        int* sdst = (int*)(dsm + 128 * TSTR);    // 128 ints
        #pragma unroll
        for (int mf = 0; mf < 4; mf++) {
            #pragma unroll
            for (int half = 0; half < 2; half++) {
                int lr = warpM + mf * 16 + (lane >> 2) + half * 8;
                int r = row0 + lr;
                bool ok = r < M;
                int sn = ok ? srcs[r] : 0;
                #pragma unroll
                for (int nf = 0; nf < NF; nf++) {
                    int cc = warpN + nf * 8 + ((lane & 3) << 1);
                    float v0 = 0.f, v1 = 0.f;
                    if (ok) {
                        v0 = acc[mf][nf][half * 2 + 0] + bias[cc];
                        v1 = acc[mf][nf][half * 2 + 1] + bias[cc + 1];
                        float at = __ldg(ATT + (size_t)r * 8 + (cc >> 4));
                        v0 = sigmoid_f(v0) * at * __ldg(V + (size_t)sn * 128 + cc);
                        v1 = sigmoid_f(v1) * at * __ldg(V + (size_t)sn * 128 + cc + 1);
                    }
                    tile[lr * TSTR + cc] = v0;
                    tile[lr * TSTR + cc + 1] = v1;
                }
            }
        }
        if (tid < 128) {
            int ge = row0 + tid;
            sdst[tid] = (ge < M) ? dsts[ge] : -1;
        }
        __syncthreads();
        // 256 threads: col = tid&127, half = tid>>7 handles rows [half*64, half*64+64)
        int c = tid & 127, rbeg = (tid >> 7) * 64, rend = rbeg + 64;
        float accum = 0.f;
        int curd = sdst[rbeg];
        if (curd >= 0) {
            for (int r = rbeg; r < rend; r++) {
                int d = sdst[r];
                if (d < 0) break;
                if (d != curd) {
                    atomicAdd(&C[(size_t)curd * 128 + c], accum);
                    accum = 0.f;
                    curd = d;
                }
                accum += tile[r * TSTR + c];
            }
            atomicAdd(&C[(size_t)curd * 128 + c], accum);
        }
        return;
    }

    // ---- normal epilogue ----
    #pragma unroll
    for (int mf = 0; mf < 4; mf++) {
        #pragma unroll
        for (int half = 0; half < 2; half++) {
            int r = row0 + warpM + mf * 16 + (lane >> 2) + half * 8;
            if (r >= M) continue;
            #pragma unroll
            for (int nf = 0; nf < NF; nf++) {
                int cc = col0 + warpN + nf * 8 + ((lane & 3) << 1);
                float v0 = acc[mf][nf][half * 2 + 0];
                float v1 = acc[mf][nf][half * 2 + 1];
                if (bias) { v0 += bias[cc]; v1 += bias[cc + 1]; }
                size_t idx = (size_t)r * N + cc;
                if (mode == 1) {
                    v0 = gelu_f(v0); v1 = gelu_f(v1);
                } else if (mode == 2) {
                    v0 += res[idx]; v1 += res[idx + 1];
                } else if (mode == 3) {
                    v0 = res[idx] + gam[idx] * v0 + bet[idx];
                    v1 = res[idx + 1] + gam[idx + 1] * v1 + bet[idx + 1];
                }
                *(float2*)(C + idx) = make_float2(v0, v1);
            }
        }
    }
}

// ---------------- LayerNorm -------------------------------------------------
__global__ void ln_kernel(const float* __restrict__ X, const float* __restrict__ G,
                          const float* __restrict__ B, float* __restrict__ O, int Nrows) {
    int warp = (blockIdx.x * blockDim.x + threadIdx.x) >> 5;
    int lane = threadIdx.x & 31;
    if (warp >= Nrows) return;
    const float* xp = X + (size_t)warp * 128;
    float4 v = *(const float4*)(xp + lane * 4);
    float s = v.x + v.y + v.z + v.w;
    #pragma unroll
    for (int o = 16; o; o >>= 1) s += __shfl_xor_sync(0xffffffffu, s, o);
    float mean = s * (1.0f / 128.0f);
    float d0 = v.x - mean, d1 = v.y - mean, d2 = v.z - mean, d3 = v.w - mean;
    float ss = d0 * d0 + d1 * d1 + d2 * d2 + d3 * d3;
    #pragma unroll
    for (int o = 16; o; o >>= 1) ss += __shfl_xor_sync(0xffffffffu, ss, o);
    float inv = rsqrtf(ss * (1.0f / 128.0f) + 1e-5f);
    float* op = O + (size_t)warp * 128;
    int c = lane * 4;
    op[c + 0] = d0 * inv * G[c + 0] + B[c + 0];
    op[c + 1] = d1 * inv * G[c + 1] + B[c + 1];
    op[c + 2] = d2 * inv * G[c + 2] + B[c + 2];
    op[c + 3] = d3 * inv * G[c + 3] + B[c + 3];
}

// ---------------- counting sort of edges by dst -----------------------------
__global__ void hist_kernel(const int* __restrict__ EI, int* __restrict__ cnt, int E) {
    int e = blockIdx.x * 256 + threadIdx.x;
    if (e < E) atomicAdd(&cnt[EI[E + e]], 1);
}
__global__ void scan1_kernel(const int* __restrict__ cnt, int* __restrict__ excl,
                             int* __restrict__ bsum, int N) {
    __shared__ int sm[256];
    int t = threadIdx.x, i = blockIdx.x * 256 + t;
    int v = (i < N) ? cnt[i] : 0;
    sm[t] = v; __syncthreads();
    for (int o = 1; o < 256; o <<= 1) {
        int a = (t >= o) ? sm[t - o] : 0;
        __syncthreads();
        sm[t] += a;
        __syncthreads();
    }
    if (i < N) excl[i] = sm[t] - v;
    if (t == 255) bsum[blockIdx.x] = sm[255];
}
__global__ void scan2_kernel(const int* __restrict__ bsum, int* __restrict__ bsumex, int nb) {
    __shared__ int sm[256];
    int t = threadIdx.x;
    int v = (t < nb) ? bsum[t] : 0;
    sm[t] = v; __syncthreads();
    for (int o = 1; o < 256; o <<= 1) {
        int a = (t >= o) ? sm[t - o] : 0;
        __syncthreads();
        sm[t] += a;
        __syncthreads();
    }
    bsumex[t] = sm[t] - v;
}
__global__ void scan3_kernel(int* __restrict__ rowstart, int* __restrict__ cursor,
                             const int* __restrict__ bsumex, int N, int E) {
    int i = blockIdx.x * 256 + threadIdx.x;
    if (i < N) {
        int v = rowstart[i] + bsumex[blockIdx.x];
        rowstart[i] = v;
        cursor[i] = v;
        if (i == N - 1) rowstart[N] = E;
    }
}
__global__ void scatter_kernel(const int* __restrict__ EI, int* __restrict__ cursor,
                               int* __restrict__ perm, int* __restrict__ srcs,
                               int* __restrict__ dsts, int E) {
    int e = blockIdx.x * 256 + threadIdx.x;
    if (e >= E) return;
    int d = EI[E + e];
    int pos = atomicAdd(&cursor[d], 1);
    perm[pos] = e;
    srcs[pos] = EI[e];
    dsts[pos] = d;
}

// ---------------- logits (sorted order), fused ea-MLP -----------------------
__global__ void logits_kernel(const float* __restrict__ EA, const int* __restrict__ perm,
                              const int* __restrict__ srcs, const int* __restrict__ dsts,
                              const float* __restrict__ W1, const float* __restrict__ B1,
                              const float* __restrict__ W2, const float* __restrict__ B2,
                              const float* __restrict__ Q, const float* __restrict__ Kk,
                              float* __restrict__ LOG, int E) {
    __shared__ float attr[64][33];
    __shared__ float w1s[32][65];
    __shared__ float ha[64][65];
    __shared__ float w2s[64][9];
    __shared__ float b2s[8];
    __shared__ int s_src[64], s_dst[64], s_perm[64];
    const int tid = threadIdx.x;
    const int e0 = blockIdx.x * 64;
    if (tid < 64) {
        int ge = e0 + tid;
        bool ok = ge < E;
        s_perm[tid] = ok ? perm[ge] : 0;
        s_src[tid] = ok ? srcs[ge] : 0;
        s_dst[tid] = ok ? dsts[ge] : 0;
    }
    for (int i = tid; i < 32 * 64; i += 256) w1s[i >> 6][i & 63] = W1[i];
    for (int i = tid; i < 64 * 8; i += 256) w2s[i >> 3][i & 7] = W2[i];
    if (tid < 8) b2s[tid] = B2[tid];
    __syncthreads();
    for (int i = tid; i < 64 * 32; i += 256) {
        int e = i >> 5, f = i & 31;
        attr[e][f] = (e0 + e < E) ? EA[(size_t)s_perm[e] * 32 + f] : 0.0f;
    }
    __syncthreads();
    {
        const int tx = tid & 15, ty = tid >> 4;
        float acc[4][4] = {};
        for (int k = 0; k < 32; k++) {
            float a[4], b[4];
            #pragma unroll
            for (int i = 0; i < 4; i++) a[i] = attr[(ty << 2) + i][k];
            #pragma unroll
            for (int j = 0; j < 4; j++) b[j] = w1s[k][(tx << 2) + j];
            #pragma unroll
            for (int i = 0; i < 4; i++)
                #pragma unroll
                for (int j = 0; j < 4; j++) acc[i][j] = fmaf(a[i], b[j], acc[i][j]);
        }
        #pragma unroll
        for (int i = 0; i < 4; i++)
            #pragma unroll
            for (int j = 0; j < 4; j++)
                ha[(ty << 2) + i][(tx << 2) + j] =
                    gelu_f(acc[i][j] + __ldg(B1 + (tx << 2) + j));
    }
    __syncthreads();
    for (int i = tid; i < 512; i += 256) {
        int e = i >> 3, h = i & 7;
        int ge = e0 + e;
        if (ge >= E) continue;
        const float* qp = Q + (size_t)s_dst[e] * 128 + h * 16;
        const float* kp = Kk + (size_t)s_src[e] * 128 + h * 16;
        float lg = 0.0f;
        #pragma unroll
        for (int d = 0; d < 16; d += 4) {
            float4 qv = *(const float4*)(qp + d);
            float4 kv = *(const float4*)(kp + d);
            lg += qv.x * kv.x + qv.y * kv.y + qv.z * kv.z + qv.w * kv.w;
        }
        lg *= 0.25f;
        float a = b2s[h];
        #pragma unroll 8
        for (int k = 0; k < 64; k++) a = fmaf(ha[e][k], w2s[k][h], a);
        LOG[(size_t)ge * 8 + h] = lg + a;
    }
}

// ---------------- per-node softmax ------------------------------------------
__global__ void softmax_kernel(const float* __restrict__ LOG, const int* __restrict__ rowstart,
                               float* __restrict__ ATT, int N) {
    int warp = (blockIdx.x * blockDim.x + threadIdx.x) >> 5;
    int lane = threadIdx.x & 31;
    if (warp >= N) return;
    int s0 = rowstart[warp], s1 = rowstart[warp + 1];
    int eo = lane >> 3, h = lane & 7;
    float m = 0.0f;
    for (int i = s0 + eo; i < s1; i += 4) m = fmaxf(m, LOG[(size_t)i * 8 + h]);
    m = fmaxf(m, __shfl_xor_sync(0xffffffffu, m, 8));
    m = fmaxf(m, __shfl_xor_sync(0xffffffffu, m, 16));
    float s = 0.0f;
    for (int i = s0 + eo; i < s1; i += 4) s += expf(LOG[(size_t)i * 8 + h] - m);
    s += __shfl_xor_sync(0xffffffffu, s, 8);
    s += __shfl_xor_sync(0xffffffffu, s, 16);
    float inv = 1.0f / (s + 1e-10f);
    for (int i = s0 + eo; i < s1; i += 4)
        ATT[(size_t)i * 8 + h] = expf(LOG[(size_t)i * 8 + h] - m) * inv;
}

// ---------------- launch ----------------------------------------------------
extern "C" void kernel_launch(void* const* d_in, const int* in_sizes, int n_in,
                              void* d_out, int out_size) {
    const float* x      = (const float*)d_in[0];
    const float* ea     = (const float*)d_in[1];
    const float* gamma  = (const float*)d_in[2];
    const float* beta   = (const float*)d_in[3];
    const float* Wq     = (const float*)d_in[4];
    const float* Wk     = (const float*)d_in[5];
    const float* Wv     = (const float*)d_in[6];
    const float* Wo     = (const float*)d_in[7];
    const float* bo     = (const float*)d_in[8];
    const float* ea_w1  = (const float*)d_in[9];
    const float* ea_b1  = (const float*)d_in[10];
    const float* ea_w2  = (const float*)d_in[11];
    const float* ea_b2  = (const float*)d_in[12];
    const float* eg_w1  = (const float*)d_in[13];
    const float* eg_b1  = (const float*)d_in[14];
    const float* eg_w2  = (const float*)d_in[15];
    const float* eg_b2  = (const float*)d_in[16];
    const float* ln1_g  = (const float*)d_in[17];
    const float* ln1_b  = (const float*)d_in[18];
    const float* ln2_g  = (const float*)d_in[19];
    const float* ln2_b  = (const float*)d_in[20];
    const float* ffn_w1 = (const float*)d_in[21];
    const float* ffn_b1 = (const float*)d_in[22];
    const float* ffn_w2 = (const float*)d_in[23];
    const float* ffn_b2 = (const float*)d_in[24];
    const int*   ei     = (const int*)d_in[25];

    int N = in_sizes[0] / 128;
    int E = in_sizes[25] / 2;

    float *pXN, *pQ, *pK, *pV, *pAGG, *pXMID, *pFFNH, *pHE, *pLOG, *pATT;
    int *pPerm, *pSrc, *pDst, *pCnt, *pRow, *pCur, *pBsum, *pBsumex;
    cudaGetSymbolAddress((void**)&pXN, g_XN);
    cudaGetSymbolAddress((void**)&pQ, g_Q);
    cudaGetSymbolAddress((void**)&pK, g_K);
    cudaGetSymbolAddress((void**)&pV, g_V);
    cudaGetSymbolAddress((void**)&pAGG, g_AGG);
    cudaGetSymbolAddress((void**)&pXMID, g_XMID);
    cudaGetSymbolAddress((void**)&pFFNH, g_FFNH);
    cudaGetSymbolAddress((void**)&pHE, g_HE);
    cudaGetSymbolAddress((void**)&pLOG, g_LOG);
    cudaGetSymbolAddress((void**)&pATT, g_ATT);
    cudaGetSymbolAddress((void**)&pPerm, g_perm);
    cudaGetSymbolAddress((void**)&pSrc, g_srcs);
    cudaGetSymbolAddress((void**)&pDst, g_dsts);
    cudaGetSymbolAddress((void**)&pCnt, g_cnt);
    cudaGetSymbolAddress((void**)&pRow, g_rowstart);
    cudaGetSymbolAddress((void**)&pCur, g_cursor);
    cudaGetSymbolAddress((void**)&pBsum, g_bsum);
    cudaGetSymbolAddress((void**)&pBsumex, g_bsumex);

    // dyn smem: 2 stages of (A 128x36 + B 32x(BN+4)) floats; mode-5 tile fits inside
    const int smem128 = (2 * 128 * 36 + 2 * 32 * 132) * 4;   // 70656
    const int smem64  = (2 * 128 * 36 + 2 * 32 * 68) * 4;    // 54272
    cudaFuncSetAttribute(mma2<128>, cudaFuncAttributeMaxDynamicSharedMemorySize, smem128);
    cudaFuncSetAttribute(mma2<64>, cudaFuncAttributeMaxDynamicSharedMemorySize, smem64);

    int nb = (N + 255) / 256;
    int lnBlocks = (N * 32 + 255) / 256;
    dim3 gn(1, (N + 127) / 128);
    dim3 ge(1, (E + 127) / 128);

    // launch order: memset,memset,ln,Q,K -> ncu -s 5 captures mma2 (K projection)
    cudaMemsetAsync(pCnt, 0, (size_t)N * sizeof(int));                       // 1
    cudaMemsetAsync(pAGG, 0, (size_t)N * 128 * sizeof(float));               // 2
    ln_kernel<<<lnBlocks, 256>>>(x, ln1_g, ln1_b, pXN, N);                   // 3
    mma2<128><<<gn, 256, smem128>>>(pXN, Wq, nullptr, nullptr, nullptr, nullptr,
        nullptr, nullptr, nullptr, nullptr, pQ, N, 128, 128, 0, nullptr);    // 4
    mma2<128><<<gn, 256, smem128>>>(pXN, Wk, nullptr, nullptr, nullptr, nullptr,
        nullptr, nullptr, nullptr, nullptr, pK, N, 128, 128, 0, nullptr);    // 5 <- profiled
    mma2<128><<<gn, 256, smem128>>>(pXN, Wv, nullptr, nullptr, nullptr, nullptr,
        nullptr, nullptr, nullptr, nullptr, pV, N, 128, 128, 0, nullptr);
    hist_kernel<<<(E + 255) / 256, 256>>>(ei, pCnt, E);
    scan1_kernel<<<nb, 256>>>(pCnt, pRow, pBsum, N);
    scan2_kernel<<<1, 256>>>(pBsum, pBsumex, nb);
    scan3_kernel<<<nb, 256>>>(pRow, pCur, pBsumex, N, E);
    scatter_kernel<<<(E + 255) / 256, 256>>>(ei, pCur, pPerm, pSrc, pDst, E);

    logits_kernel<<<(E + 63) / 64, 256>>>(ea, pPerm, pSrc, pDst, ea_w1, ea_b1, ea_w2, ea_b2,
                                          pQ, pK, pLOG, E);
    softmax_kernel<<<(N * 32 + 255) / 256, 256>>>(pLOG, pRow, pATT, N);
    // HG = gelu(EA[perm] @ eg_w1 + b1)   [E, 64], K=32
    mma2<64><<<ge, 256, smem64>>>(ea, eg_w1, eg_b1, nullptr, nullptr, nullptr,
        nullptr, nullptr, nullptr, nullptr, pHE, E, 64, 32, 1, pPerm);
    // AGG += segreduce(sigmoid(HG @ eg_w2 + b2) * att * V[src])   mode 5
    mma2<128><<<ge, 256, smem128>>>(pHE, eg_w2, eg_b2, nullptr, nullptr, nullptr,
        pV, pSrc, pDst, pATT, pAGG, E, 128, 64, 5, nullptr);

    mma2<128><<<gn, 256, smem128>>>(pAGG, Wo, bo, x, gamma, beta,
        nullptr, nullptr, nullptr, nullptr, pXMID, N, 128, 128, 3, nullptr);
    ln_kernel<<<lnBlocks, 256>>>(pXMID, ln2_g, ln2_b, pXN, N);
    dim3 gn2(2, (N + 127) / 128);
    mma2<128><<<gn2, 256, smem128>>>(pXN, ffn_w1, ffn_b1, nullptr, nullptr, nullptr,
        nullptr, nullptr, nullptr, nullptr, pFFNH, N, 256, 128, 1, nullptr);
    mma2<128><<<gn, 256, smem128>>>(pFFNH, ffn_w2, ffn_b2, pXMID, nullptr, nullptr,
        nullptr, nullptr, nullptr, nullptr, (float*)d_out, N, 128, 256, 2, nullptr);
}

// round 11
// speedup vs baseline: 1.1792x; 1.0164x over previous
#include <cuda_runtime.h>
#include <math.h>
#include <stdint.h>

#define NMAX 50000
#define EMAX 500000

// ---------------- static scratch ------------------------------------------
__device__ float g_XN[NMAX * 128];
__device__ float g_Q[NMAX * 128];
__device__ float g_K[NMAX * 128];
__device__ float g_V[NMAX * 128];
__device__ float g_AGG[NMAX * 128];
__device__ float g_XMID[NMAX * 128];
__device__ float g_FFNH[NMAX * 256];
__device__ float g_HE[EMAX * 64];
__device__ float g_LOG[EMAX * 8];
__device__ float g_ATT[EMAX * 8];
__device__ int   g_perm[EMAX];
__device__ int   g_srcs[EMAX];
__device__ int   g_dsts[EMAX];
__device__ int   g_cnt[NMAX];
__device__ int   g_rowstart[NMAX + 1];
__device__ int   g_cursor[NMAX];
__device__ int   g_bsum[256];
__device__ int   g_bsumex[256];

__device__ __forceinline__ float gelu_f(float x) {
    return 0.5f * x * (1.0f + erff(x * 0.70710678118654752f));
}
__device__ __forceinline__ float sigmoid_f(float x) {
    return 1.0f / (1.0f + expf(-x));
}

__device__ __forceinline__ void cpa16(uint32_t dst, const void* src, bool valid) {
    int sz = valid ? 16 : 0;
    asm volatile("cp.async.cg.shared.global [%0], [%1], 16, %2;"
                 :: "r"(dst), "l"(src), "r"(sz) : "memory");
}
#define CP_COMMIT() asm volatile("cp.async.commit_group;" ::: "memory")
template <int Ng>
__device__ __forceinline__ void cp_wait() {
    asm volatile("cp.async.wait_group %0;" :: "n"(Ng) : "memory");
}

__device__ __forceinline__ void mma_tf32(float* c, const unsigned* a, const unsigned* b) {
    asm volatile(
        "mma.sync.aligned.m16n8k8.row.col.f32.tf32.tf32.f32 "
        "{%0,%1,%2,%3}, {%4,%5,%6,%7}, {%8,%9}, {%0,%1,%2,%3};"
        : "+f"(c[0]), "+f"(c[1]), "+f"(c[2]), "+f"(c[3])
        : "r"(a[0]), "r"(a[1]), "r"(a[2]), "r"(a[3]), "r"(b[0]), "r"(b[1]));
}
__device__ __forceinline__ void ldsm_x4(unsigned* a, uint32_t addr) {
    asm volatile("ldmatrix.sync.aligned.m8n8.x4.shared.b16 {%0,%1,%2,%3}, [%4];"
                 : "=r"(a[0]), "=r"(a[1]), "=r"(a[2]), "=r"(a[3]) : "r"(addr));
}

// ---------------- tf32 mma GEMM: 2-stage cp.async + ldmatrix A + mode5 ------
// 128 rows x BN cols per CTA, BK=32, 8 warps.
// modes: 0:+bias 1:gelu 2:res+ 3:res+gam*+bet
//        5: gate+reduce: v=sigmoid(+bias)*ATT*V[srcs[row]]; rows are dst-sorted
//           edges; CTA reduces consecutive equal-dst rows in smem and
//           atomicAdds per-segment sums into C (=AGG, zero-initialized).
template <int BN>
__global__ void __launch_bounds__(256, 2) mma2(
        const float* __restrict__ A, const float* __restrict__ W,
        const float* __restrict__ bias, const float* __restrict__ res,
        const float* __restrict__ gam, const float* __restrict__ bet,
        const float* __restrict__ V, const int* __restrict__ srcs,
        const int* __restrict__ dsts, const float* __restrict__ ATT,
        float* __restrict__ C, int M, int N, int K, int mode,
        const int* __restrict__ rowidx) {
    constexpr int NF = BN / 32;
    constexpr int WN = BN / 4;
    constexpr int ASTR = 36;
    constexpr int BSTR = BN + 4;
    constexpr int ASZ = 128 * ASTR;
    constexpr int BSZ = 32 * BSTR;
    constexpr int BCH = (32 * (BN / 4)) / 256;
    extern __shared__ float dsm[];
    float* Abuf = dsm;
    float* Bbuf = dsm + 2 * ASZ;
    const uint32_t aAddr = (uint32_t)__cvta_generic_to_shared(Abuf);
    const uint32_t bAddr = (uint32_t)__cvta_generic_to_shared(Bbuf);
    const int tid = threadIdx.x, lane = tid & 31, wid = tid >> 5;
    const int wm = wid & 1, wn = wid >> 1;
    const int row0 = blockIdx.y * 128, col0 = blockIdx.x * BN;
    const int warpM = wm * 64, warpN = wn * WN;
    // ldmatrix lane offset: g=lane>>3 selects sub-matrix {rows 0-7/8-15} x {k 0-3/4-7}
    const int g = lane >> 3, rl = lane & 7;
    const uint32_t aLaneOff = (uint32_t)(((rl + (g & 1) * 8) * ASTR + (g >> 1) * 4) * 4);
    float acc[4][NF][4];
    #pragma unroll
    for (int i = 0; i < 4; i++)
        #pragma unroll
        for (int j = 0; j < NF; j++) {
            acc[i][j][0] = 0.f; acc[i][j][1] = 0.f; acc[i][j][2] = 0.f; acc[i][j][3] = 0.f;
        }

    const int ntiles = K >> 5;

    auto load_tile = [&](int stage, int t) {
        const int kt = t << 5;
        uint32_t ab = aAddr + stage * (ASZ * 4);
        #pragma unroll
        for (int it = 0; it < 4; it++) {
            int cI = tid + it * 256;
            int r = cI >> 3, q = cI & 7;
            int gr = row0 + r;
            bool v = gr < M;
            const float* src = A;
            if (v) {
                int pr = rowidx ? rowidx[gr] : gr;
                src = A + (size_t)pr * K + kt + q * 4;
            }
            cpa16(ab + (uint32_t)(r * ASTR + q * 4) * 4, src, v);
        }
        uint32_t bb = bAddr + stage * (BSZ * 4);
        #pragma unroll
        for (int it = 0; it < BCH; it++) {
            int cI = tid + it * 256;
            int kr = cI / (BN / 4), q = cI % (BN / 4);
            cpa16(bb + (uint32_t)(kr * BSTR + q * 4) * 4,
                  W + (size_t)(kt + kr) * N + col0 + q * 4, true);
        }
    };

    load_tile(0, 0);
    CP_COMMIT();
    for (int t = 0; t < ntiles; t++) {
        int cur = t & 1;
        if (t + 1 < ntiles) {
            load_tile(1 - cur, t + 1);
            CP_COMMIT();
            cp_wait<1>();
        } else {
            cp_wait<0>();
        }
        __syncthreads();
        const uint32_t aWarp = aAddr + (uint32_t)(cur * ASZ) * 4 +
                               (uint32_t)(warpM * ASTR) * 4 + aLaneOff;
        const float* Bb = Bbuf + cur * BSZ;
        #pragma unroll
        for (int ks = 0; ks < 4; ks++) {
            int k = ks * 8 + (lane & 3);
            unsigned af[4][4];
            #pragma unroll
            for (int mf = 0; mf < 4; mf++)
                ldsm_x4(af[mf], aWarp + (uint32_t)(mf * 16 * ASTR * 4 + ks * 32));
            unsigned bf[NF][2];
            #pragma unroll
            for (int nf = 0; nf < NF; nf++) {
                int n0 = warpN + nf * 8 + (lane >> 2);
                bf[nf][0] = __float_as_uint(Bb[k * BSTR + n0]);
                bf[nf][1] = __float_as_uint(Bb[(k + 4) * BSTR + n0]);
            }
            #pragma unroll
            for (int mf = 0; mf < 4; mf++)
                #pragma unroll
                for (int nf = 0; nf < NF; nf++)
                    mma_tf32(acc[mf][nf], af[mf], bf[nf]);
        }
        __syncthreads();
    }

    if (mode == 5) {
        // ---- fused gate epilogue + per-dst segment reduction ----
        constexpr int TSTR = 132;
        float* tile = dsm;                       // 128 x 132 floats (reuse pipeline smem)
        int* sdst = (int*)(dsm + 128 * TSTR);    // 128 ints
        #pragma unroll
        for (int mf = 0; mf < 4; mf++) {
            #pragma unroll
            for (int half = 0; half < 2; half++) {
                int lr = warpM + mf * 16 + (lane >> 2) + half * 8;
                int r = row0 + lr;
                bool ok = r < M;
                int sn = ok ? srcs[r] : 0;
                #pragma unroll
                for (int nf = 0; nf < NF; nf++) {
                    int cc = warpN + nf * 8 + ((lane & 3) << 1);
                    float v0 = 0.f, v1 = 0.f;
                    if (ok) {
                        v0 = acc[mf][nf][half * 2 + 0] + bias[cc];
                        v1 = acc[mf][nf][half * 2 + 1] + bias[cc + 1];
                        float at = __ldg(ATT + (size_t)r * 8 + (cc >> 4));
                        v0 = sigmoid_f(v0) * at * __ldg(V + (size_t)sn * 128 + cc);
                        v1 = sigmoid_f(v1) * at * __ldg(V + (size_t)sn * 128 + cc + 1);
                    }
                    tile[lr * TSTR + cc] = v0;
                    tile[lr * TSTR + cc + 1] = v1;
                }
            }
        }
        if (tid < 128) {
            int ge = row0 + tid;
            sdst[tid] = (ge < M) ? dsts[ge] : -1;
        }
        __syncthreads();
        int c = tid & 127, rbeg = (tid >> 7) * 64, rend = rbeg + 64;
        float accum = 0.f;
        int curd = sdst[rbeg];
        if (curd >= 0) {
            for (int r = rbeg; r < rend; r++) {
                int d = sdst[r];
                if (d < 0) break;
                if (d != curd) {
                    atomicAdd(&C[(size_t)curd * 128 + c], accum);
                    accum = 0.f;
                    curd = d;
                }
                accum += tile[r * TSTR + c];
            }
            atomicAdd(&C[(size_t)curd * 128 + c], accum);
        }
        return;
    }

    // ---- normal epilogue ----
    #pragma unroll
    for (int mf = 0; mf < 4; mf++) {
        #pragma unroll
        for (int half = 0; half < 2; half++) {
            int r = row0 + warpM + mf * 16 + (lane >> 2) + half * 8;
            if (r >= M) continue;
            #pragma unroll
            for (int nf = 0; nf < NF; nf++) {
                int cc = col0 + warpN + nf * 8 + ((lane & 3) << 1);
                float v0 = acc[mf][nf][half * 2 + 0];
                float v1 = acc[mf][nf][half * 2 + 1];
                if (bias) { v0 += bias[cc]; v1 += bias[cc + 1]; }
                size_t idx = (size_t)r * N + cc;
                if (mode == 1) {
                    v0 = gelu_f(v0); v1 = gelu_f(v1);
                } else if (mode == 2) {
                    v0 += res[idx]; v1 += res[idx + 1];
                } else if (mode == 3) {
                    v0 = res[idx] + gam[idx] * v0 + bet[idx];
                    v1 = res[idx + 1] + gam[idx + 1] * v1 + bet[idx + 1];
                }
                *(float2*)(C + idx) = make_float2(v0, v1);
            }
        }
    }
}

// ---------------- LayerNorm -------------------------------------------------
__global__ void ln_kernel(const float* __restrict__ X, const float* __restrict__ G,
                          const float* __restrict__ B, float* __restrict__ O, int Nrows) {
    int warp = (blockIdx.x * blockDim.x + threadIdx.x) >> 5;
    int lane = threadIdx.x & 31;
    if (warp >= Nrows) return;
    const float* xp = X + (size_t)warp * 128;
    float4 v = *(const float4*)(xp + lane * 4);
    float s = v.x + v.y + v.z + v.w;
    #pragma unroll
    for (int o = 16; o; o >>= 1) s += __shfl_xor_sync(0xffffffffu, s, o);
    float mean = s * (1.0f / 128.0f);
    float d0 = v.x - mean, d1 = v.y - mean, d2 = v.z - mean, d3 = v.w - mean;
    float ss = d0 * d0 + d1 * d1 + d2 * d2 + d3 * d3;
    #pragma unroll
    for (int o = 16; o; o >>= 1) ss += __shfl_xor_sync(0xffffffffu, ss, o);
    float inv = rsqrtf(ss * (1.0f / 128.0f) + 1e-5f);
    float* op = O + (size_t)warp * 128;
    int c = lane * 4;
    op[c + 0] = d0 * inv * G[c + 0] + B[c + 0];
    op[c + 1] = d1 * inv * G[c + 1] + B[c + 1];
    op[c + 2] = d2 * inv * G[c + 2] + B[c + 2];
    op[c + 3] = d3 * inv * G[c + 3] + B[c + 3];
}

// ---------------- counting sort of edges by dst -----------------------------
__global__ void hist_kernel(const int* __restrict__ EI, int* __restrict__ cnt, int E) {
    int e = blockIdx.x * 256 + threadIdx.x;
    if (e < E) atomicAdd(&cnt[EI[E + e]], 1);
}
__global__ void scan1_kernel(const int* __restrict__ cnt, int* __restrict__ excl,
                             int* __restrict__ bsum, int N) {
    __shared__ int sm[256];
    int t = threadIdx.x, i = blockIdx.x * 256 + t;
    int v = (i < N) ? cnt[i] : 0;
    sm[t] = v; __syncthreads();
    for (int o = 1; o < 256; o <<= 1) {
        int a = (t >= o) ? sm[t - o] : 0;
        __syncthreads();
        sm[t] += a;
        __syncthreads();
    }
    if (i < N) excl[i] = sm[t] - v;
    if (t == 255) bsum[blockIdx.x] = sm[255];
}
__global__ void scan2_kernel(const int* __restrict__ bsum, int* __restrict__ bsumex, int nb) {
    __shared__ int sm[256];
    int t = threadIdx.x;
    int v = (t < nb) ? bsum[t] : 0;
    sm[t] = v; __syncthreads();
    for (int o = 1; o < 256; o <<= 1) {
        int a = (t >= o) ? sm[t - o] : 0;
        __syncthreads();
        sm[t] += a;
        __syncthreads();
    }
    bsumex[t] = sm[t] - v;
}
__global__ void scan3_kernel(int* __restrict__ rowstart, int* __restrict__ cursor,
                             const int* __restrict__ bsumex, int N, int E) {
    int i = blockIdx.x * 256 + threadIdx.x;
    if (i < N) {
        int v = rowstart[i] + bsumex[blockIdx.x];
        rowstart[i] = v;
        cursor[i] = v;
        if (i == N - 1) rowstart[N] = E;
    }
}
__global__ void scatter_kernel(const int* __restrict__ EI, int* __restrict__ cursor,
                               int* __restrict__ perm, int* __restrict__ srcs,
                               int* __restrict__ dsts, int E) {
    int e = blockIdx.x * 256 + threadIdx.x;
    if (e >= E) return;
    int d = EI[E + e];
    int pos = atomicAdd(&cursor[d], 1);
    perm[pos] = e;
    srcs[pos] = EI[e];
    dsts[pos] = d;
}

// ---------------- logits (sorted order), fused ea-MLP -----------------------
__global__ void logits_kernel(const float* __restrict__ EA, const int* __restrict__ perm,
                              const int* __restrict__ srcs, const int* __restrict__ dsts,
                              const float* __restrict__ W1, const float* __restrict__ B1,
                              const float* __restrict__ W2, const float* __restrict__ B2,
                              const float* __restrict__ Q, const float* __restrict__ Kk,
                              float* __restrict__ LOG, int E) {
    __shared__ float attr[64][33];
    __shared__ float w1s[32][65];
    __shared__ float ha[64][65];
    __shared__ float w2s[64][9];
    __shared__ float b2s[8];
    __shared__ int s_src[64], s_dst[64], s_perm[64];
    const int tid = threadIdx.x;
    const int e0 = blockIdx.x * 64;
    if (tid < 64) {
        int ge = e0 + tid;
        bool ok = ge < E;
        s_perm[tid] = ok ? perm[ge] : 0;
        s_src[tid] = ok ? srcs[ge] : 0;
        s_dst[tid] = ok ? dsts[ge] : 0;
    }
    for (int i = tid; i < 32 * 64; i += 256) w1s[i >> 6][i & 63] = W1[i];
    for (int i = tid; i < 64 * 8; i += 256) w2s[i >> 3][i & 7] = W2[i];
    if (tid < 8) b2s[tid] = B2[tid];
    __syncthreads();
    for (int i = tid; i < 64 * 32; i += 256) {
        int e = i >> 5, f = i & 31;
        attr[e][f] = (e0 + e < E) ? EA[(size_t)s_perm[e] * 32 + f] : 0.0f;
    }
    __syncthreads();
    {
        const int tx = tid & 15, ty = tid >> 4;
        float acc[4][4] = {};
        for (int k = 0; k < 32; k++) {
            float a[4], b[4];
            #pragma unroll
            for (int i = 0; i < 4; i++) a[i] = attr[(ty << 2) + i][k];
            #pragma unroll
            for (int j = 0; j < 4; j++) b[j] = w1s[k][(tx << 2) + j];
            #pragma unroll
            for (int i = 0; i < 4; i++)
                #pragma unroll
                for (int j = 0; j < 4; j++) acc[i][j] = fmaf(a[i], b[j], acc[i][j]);
        }
        #pragma unroll
        for (int i = 0; i < 4; i++)
            #pragma unroll
            for (int j = 0; j < 4; j++)
                ha[(ty << 2) + i][(tx << 2) + j] =
                    gelu_f(acc[i][j] + __ldg(B1 + (tx << 2) + j));
    }
    __syncthreads();
    for (int i = tid; i < 512; i += 256) {
        int e = i >> 3, h = i & 7;
        int ge = e0 + e;
        if (ge >= E) continue;
        const float* qp = Q + (size_t)s_dst[e] * 128 + h * 16;
        const float* kp = Kk + (size_t)s_src[e] * 128 + h * 16;
        float lg = 0.0f;
        #pragma unroll
        for (int d = 0; d < 16; d += 4) {
            float4 qv = *(const float4*)(qp + d);
            float4 kv = *(const float4*)(kp + d);
            lg += qv.x * kv.x + qv.y * kv.y + qv.z * kv.z + qv.w * kv.w;
        }
        lg *= 0.25f;
        float a = b2s[h];
        #pragma unroll 8
        for (int k = 0; k < 64; k++) a = fmaf(ha[e][k], w2s[k][h], a);
        LOG[(size_t)ge * 8 + h] = lg + a;
    }
}

// ---------------- per-node softmax ------------------------------------------
__global__ void softmax_kernel(const float* __restrict__ LOG, const int* __restrict__ rowstart,
                               float* __restrict__ ATT, int N) {
    int warp = (blockIdx.x * blockDim.x + threadIdx.x) >> 5;
    int lane = threadIdx.x & 31;
    if (warp >= N) return;
    int s0 = rowstart[warp], s1 = rowstart[warp + 1];
    int eo = lane >> 3, h = lane & 7;
    float m = 0.0f;
    for (int i = s0 + eo; i < s1; i += 4) m = fmaxf(m, LOG[(size_t)i * 8 + h]);
    m = fmaxf(m, __shfl_xor_sync(0xffffffffu, m, 8));
    m = fmaxf(m, __shfl_xor_sync(0xffffffffu, m, 16));
    float s = 0.0f;
    for (int i = s0 + eo; i < s1; i += 4) s += expf(LOG[(size_t)i * 8 + h] - m);
    s += __shfl_xor_sync(0xffffffffu, s, 8);
    s += __shfl_xor_sync(0xffffffffu, s, 16);
    float inv = 1.0f / (s + 1e-10f);
    for (int i = s0 + eo; i < s1; i += 4)
        ATT[(size_t)i * 8 + h] = expf(LOG[(size_t)i * 8 + h] - m) * inv;
}

// ---------------- launch ----------------------------------------------------
extern "C" void kernel_launch(void* const* d_in, const int* in_sizes, int n_in,
                              void* d_out, int out_size) {
    const float* x      = (const float*)d_in[0];
    const float* ea     = (const float*)d_in[1];
    const float* gamma  = (const float*)d_in[2];
    const float* beta   = (const float*)d_in[3];
    const float* Wq     = (const float*)d_in[4];
    const float* Wk     = (const float*)d_in[5];
    const float* Wv     = (const float*)d_in[6];
    const float* Wo     = (const float*)d_in[7];
    const float* bo     = (const float*)d_in[8];
    const float* ea_w1  = (const float*)d_in[9];
    const float* ea_b1  = (const float*)d_in[10];
    const float* ea_w2  = (const float*)d_in[11];
    const float* ea_b2  = (const float*)d_in[12];
    const float* eg_w1  = (const float*)d_in[13];
    const float* eg_b1  = (const float*)d_in[14];
    const float* eg_w2  = (const float*)d_in[15];
    const float* eg_b2  = (const float*)d_in[16];
    const float* ln1_g  = (const float*)d_in[17];
    const float* ln1_b  = (const float*)d_in[18];
    const float* ln2_g  = (const float*)d_in[19];
    const float* ln2_b  = (const float*)d_in[20];
    const float* ffn_w1 = (const float*)d_in[21];
    const float* ffn_b1 = (const float*)d_in[22];
    const float* ffn_w2 = (const float*)d_in[23];
    const float* ffn_b2 = (const float*)d_in[24];
    const int*   ei     = (const int*)d_in[25];

    int N = in_sizes[0] / 128;
    int E = in_sizes[25] / 2;

    float *pXN, *pQ, *pK, *pV, *pAGG, *pXMID, *pFFNH, *pHE, *pLOG, *pATT;
    int *pPerm, *pSrc, *pDst, *pCnt, *pRow, *pCur, *pBsum, *pBsumex;
    cudaGetSymbolAddress((void**)&pXN, g_XN);
    cudaGetSymbolAddress((void**)&pQ, g_Q);
    cudaGetSymbolAddress((void**)&pK, g_K);
    cudaGetSymbolAddress((void**)&pV, g_V);
    cudaGetSymbolAddress((void**)&pAGG, g_AGG);
    cudaGetSymbolAddress((void**)&pXMID, g_XMID);
    cudaGetSymbolAddress((void**)&pFFNH, g_FFNH);
    cudaGetSymbolAddress((void**)&pHE, g_HE);
    cudaGetSymbolAddress((void**)&pLOG, g_LOG);
    cudaGetSymbolAddress((void**)&pATT, g_ATT);
    cudaGetSymbolAddress((void**)&pPerm, g_perm);
    cudaGetSymbolAddress((void**)&pSrc, g_srcs);
    cudaGetSymbolAddress((void**)&pDst, g_dsts);
    cudaGetSymbolAddress((void**)&pCnt, g_cnt);
    cudaGetSymbolAddress((void**)&pRow, g_rowstart);
    cudaGetSymbolAddress((void**)&pCur, g_cursor);
    cudaGetSymbolAddress((void**)&pBsum, g_bsum);
    cudaGetSymbolAddress((void**)&pBsumex, g_bsumex);

    const int smem128 = (2 * 128 * 36 + 2 * 32 * 132) * 4;   // 70656
    const int smem64  = (2 * 128 * 36 + 2 * 32 * 68) * 4;    // 54272
    cudaFuncSetAttribute(mma2<128>, cudaFuncAttributeMaxDynamicSharedMemorySize, smem128);
    cudaFuncSetAttribute(mma2<64>, cudaFuncAttributeMaxDynamicSharedMemorySize, smem64);

    int nb = (N + 255) / 256;
    int lnBlocks = (N * 32 + 255) / 256;
    dim3 gn(1, (N + 127) / 128);
    dim3 ge(1, (E + 127) / 128);

    // launch order: memset,memset,ln,Q,K -> ncu -s 5 captures mma2 (K projection)
    cudaMemsetAsync(pCnt, 0, (size_t)N * sizeof(int));                       // 1
    cudaMemsetAsync(pAGG, 0, (size_t)N * 128 * sizeof(float));               // 2
    ln_kernel<<<lnBlocks, 256>>>(x, ln1_g, ln1_b, pXN, N);                   // 3
    mma2<128><<<gn, 256, smem128>>>(pXN, Wq, nullptr, nullptr, nullptr, nullptr,
        nullptr, nullptr, nullptr, nullptr, pQ, N, 128, 128, 0, nullptr);    // 4
    mma2<128><<<gn, 256, smem128>>>(pXN, Wk, nullptr, nullptr, nullptr, nullptr,
        nullptr, nullptr, nullptr, nullptr, pK, N, 128, 128, 0, nullptr);    // 5 <- profiled
    mma2<128><<<gn, 256, smem128>>>(pXN, Wv, nullptr, nullptr, nullptr, nullptr,
        nullptr, nullptr, nullptr, nullptr, pV, N, 128, 128, 0, nullptr);
    hist_kernel<<<(E + 255) / 256, 256>>>(ei, pCnt, E);
    scan1_kernel<<<nb, 256>>>(pCnt, pRow, pBsum, N);
    scan2_kernel<<<1, 256>>>(pBsum, pBsumex, nb);
    scan3_kernel<<<nb, 256>>>(pRow, pCur, pBsumex, N, E);
    scatter_kernel<<<(E + 255) / 256, 256>>>(ei, pCur, pPerm, pSrc, pDst, E);

    logits_kernel<<<(E + 63) / 64, 256>>>(ea, pPerm, pSrc, pDst, ea_w1, ea_b1, ea_w2, ea_b2,
                                          pQ, pK, pLOG, E);
    softmax_kernel<<<(N * 32 + 255) / 256, 256>>>(pLOG, pRow, pATT, N);
    // HG = gelu(EA[perm] @ eg_w1 + b1)   [E, 64], K=32
    mma2<64><<<ge, 256, smem64>>>(ea, eg_w1, eg_b1, nullptr, nullptr, nullptr,
        nullptr, nullptr, nullptr, nullptr, pHE, E, 64, 32, 1, pPerm);
    // AGG += segreduce(sigmoid(HG @ eg_w2 + b2) * att * V[src])   mode 5
    mma2<128><<<ge, 256, smem128>>>(pHE, eg_w2, eg_b2, nullptr, nullptr, nullptr,
        pV, pSrc, pDst, pATT, pAGG, E, 128, 64, 5, nullptr);

    mma2<128><<<gn, 256, smem128>>>(pAGG, Wo, bo, x, gamma, beta,
        nullptr, nullptr, nullptr, nullptr, pXMID, N, 128, 128, 3, nullptr);
    ln_kernel<<<lnBlocks, 256>>>(pXMID, ln2_g, ln2_b, pXN, N);
    dim3 gn2(2, (N + 127) / 128);
    mma2<128><<<gn2, 256, smem128>>>(pXN, ffn_w1, ffn_b1, nullptr, nullptr, nullptr,
        nullptr, nullptr, nullptr, nullptr, pFFNH, N, 256, 128, 1, nullptr);
    mma2<128><<<gn, 256, smem128>>>(pFFNH, ffn_w2, ffn_b2, pXMID, nullptr, nullptr,
        nullptr, nullptr, nullptr, nullptr, (float*)d_out, N, 128, 256, 2, nullptr);
}

// round 12
// speedup vs baseline: 1.2314x; 1.0443x over previous
#include <cuda_runtime.h>
#include <math.h>
#include <stdint.h>

#define NMAX 50000
#define EMAX 500000

// ---------------- static scratch ------------------------------------------
__device__ float g_XN[NMAX * 128];
__device__ float g_QKV[NMAX * 384];     // row-interleaved: Q | K | V per node
__device__ float g_WQKV[128 * 384];     // packed Wq|Wk|Wv
__device__ float g_AGG[NMAX * 128];
__device__ float g_XMID[NMAX * 128];
__device__ float g_FFNH[NMAX * 256];
__device__ float g_HE[EMAX * 64];
__device__ float g_LOG[EMAX * 8];
__device__ float g_ATT[EMAX * 8];
__device__ int   g_perm[EMAX];
__device__ int   g_srcs[EMAX];
__device__ int   g_dsts[EMAX];
__device__ int   g_cnt[NMAX];
__device__ int   g_rowstart[NMAX + 1];
__device__ int   g_cursor[NMAX];
__device__ int   g_bsum[256];
__device__ int   g_bsumex[256];

__device__ __forceinline__ float gelu_f(float x) {
    return 0.5f * x * (1.0f + erff(x * 0.70710678118654752f));
}
__device__ __forceinline__ float sigmoid_f(float x) {
    return 1.0f / (1.0f + expf(-x));
}

__device__ __forceinline__ void cpa16(uint32_t dst, const void* src, bool valid) {
    int sz = valid ? 16 : 0;
    asm volatile("cp.async.cg.shared.global [%0], [%1], 16, %2;"
                 :: "r"(dst), "l"(src), "r"(sz) : "memory");
}
#define CP_COMMIT() asm volatile("cp.async.commit_group;" ::: "memory")
template <int Ng>
__device__ __forceinline__ void cp_wait() {
    asm volatile("cp.async.wait_group %0;" :: "n"(Ng) : "memory");
}

__device__ __forceinline__ void mma_tf32(float* c, const unsigned* a, const unsigned* b) {
    asm volatile(
        "mma.sync.aligned.m16n8k8.row.col.f32.tf32.tf32.f32 "
        "{%0,%1,%2,%3}, {%4,%5,%6,%7}, {%8,%9}, {%0,%1,%2,%3};"
        : "+f"(c[0]), "+f"(c[1]), "+f"(c[2]), "+f"(c[3])
        : "r"(a[0]), "r"(a[1]), "r"(a[2]), "r"(a[3]), "r"(b[0]), "r"(b[1]));
}
__device__ __forceinline__ void ldsm_x4(unsigned* a, uint32_t addr) {
    asm volatile("ldmatrix.sync.aligned.m8n8.x4.shared.b16 {%0,%1,%2,%3}, [%4];"
                 : "=r"(a[0]), "=r"(a[1]), "=r"(a[2]), "=r"(a[3]) : "r"(addr));
}

// ---------------- tf32 mma GEMM: 2-stage cp.async + ldmatrix A --------------
// 128 rows x BN cols per CTA, BK=32, 8 warps.
// modes: 0:+bias 1:gelu 2:res+ 3:res+gam*+bet
//        5: gate+reduce: v=sigmoid(+bias)*ATT*V[srcs[row]] (V stride 384, QKV
//           V-section); dst-sorted rows segment-reduced into C via atomics.
//        6: HA+logits: tile=gelu(acc+bias); LOG[e,h] = Q[dst].K[src]/4
//           + tile[e].w2[:,h] + b2[h].  (gam=w2 [64,8], bet=b2, V=QKV base)
template <int BN>
__global__ void __launch_bounds__(256, 2) mma2(
        const float* __restrict__ A, const float* __restrict__ W,
        const float* __restrict__ bias, const float* __restrict__ res,
        const float* __restrict__ gam, const float* __restrict__ bet,
        const float* __restrict__ V, const int* __restrict__ srcs,
        const int* __restrict__ dsts, const float* __restrict__ ATT,
        float* __restrict__ C, int M, int N, int K, int mode,
        const int* __restrict__ rowidx) {
    constexpr int NF = BN / 32;
    constexpr int WN = BN / 4;
    constexpr int ASTR = 36;
    constexpr int BSTR = BN + 4;
    constexpr int ASZ = 128 * ASTR;
    constexpr int BSZ = 32 * BSTR;
    constexpr int BCH = (32 * (BN / 4)) / 256;
    extern __shared__ float dsm[];
    float* Abuf = dsm;
    float* Bbuf = dsm + 2 * ASZ;
    const uint32_t aAddr = (uint32_t)__cvta_generic_to_shared(Abuf);
    const uint32_t bAddr = (uint32_t)__cvta_generic_to_shared(Bbuf);
    const int tid = threadIdx.x, lane = tid & 31, wid = tid >> 5;
    const int wm = wid & 1, wn = wid >> 1;
    const int row0 = blockIdx.y * 128, col0 = blockIdx.x * BN;
    const int warpM = wm * 64, warpN = wn * WN;
    const int g = lane >> 3, rl = lane & 7;
    const uint32_t aLaneOff = (uint32_t)(((rl + (g & 1) * 8) * ASTR + (g >> 1) * 4) * 4);
    float acc[4][NF][4];
    #pragma unroll
    for (int i = 0; i < 4; i++)
        #pragma unroll
        for (int j = 0; j < NF; j++) {
            acc[i][j][0] = 0.f; acc[i][j][1] = 0.f; acc[i][j][2] = 0.f; acc[i][j][3] = 0.f;
        }

    const int ntiles = K >> 5;

    auto load_tile = [&](int stage, int t) {
        const int kt = t << 5;
        uint32_t ab = aAddr + stage * (ASZ * 4);
        #pragma unroll
        for (int it = 0; it < 4; it++) {
            int cI = tid + it * 256;
            int r = cI >> 3, q = cI & 7;
            int gr = row0 + r;
            bool v = gr < M;
            const float* src = A;
            if (v) {
                int pr = rowidx ? rowidx[gr] : gr;
                src = A + (size_t)pr * K + kt + q * 4;
            }
            cpa16(ab + (uint32_t)(r * ASTR + q * 4) * 4, src, v);
        }
        uint32_t bb = bAddr + stage * (BSZ * 4);
        #pragma unroll
        for (int it = 0; it < BCH; it++) {
            int cI = tid + it * 256;
            int kr = cI / (BN / 4), q = cI % (BN / 4);
            cpa16(bb + (uint32_t)(kr * BSTR + q * 4) * 4,
                  W + (size_t)(kt + kr) * N + col0 + q * 4, true);
        }
    };

    load_tile(0, 0);
    CP_COMMIT();
    for (int t = 0; t < ntiles; t++) {
        int cur = t & 1;
        if (t + 1 < ntiles) {
            load_tile(1 - cur, t + 1);
            CP_COMMIT();
            cp_wait<1>();
        } else {
            cp_wait<0>();
        }
        __syncthreads();
        const uint32_t aWarp = aAddr + (uint32_t)(cur * ASZ) * 4 +
                               (uint32_t)(warpM * ASTR) * 4 + aLaneOff;
        const float* Bb = Bbuf + cur * BSZ;
        #pragma unroll
        for (int ks = 0; ks < 4; ks++) {
            int k = ks * 8 + (lane & 3);
            unsigned af[4][4];
            #pragma unroll
            for (int mf = 0; mf < 4; mf++)
                ldsm_x4(af[mf], aWarp + (uint32_t)(mf * 16 * ASTR * 4 + ks * 32));
            unsigned bf[NF][2];
            #pragma unroll
            for (int nf = 0; nf < NF; nf++) {
                int n0 = warpN + nf * 8 + (lane >> 2);
                bf[nf][0] = __float_as_uint(Bb[k * BSTR + n0]);
                bf[nf][1] = __float_as_uint(Bb[(k + 4) * BSTR + n0]);
            }
            #pragma unroll
            for (int mf = 0; mf < 4; mf++)
                #pragma unroll
                for (int nf = 0; nf < NF; nf++)
                    mma_tf32(acc[mf][nf], af[mf], bf[nf]);
        }
        __syncthreads();
    }

    if (mode == 5) {
        // ---- fused gate epilogue + per-dst segment reduction ----
        constexpr int TSTR = 132;
        float* tile = dsm;
        int* sdst = (int*)(dsm + 128 * TSTR);
        #pragma unroll
        for (int mf = 0; mf < 4; mf++) {
            #pragma unroll
            for (int half = 0; half < 2; half++) {
                int lr = warpM + mf * 16 + (lane >> 2) + half * 8;
                int r = row0 + lr;
                bool ok = r < M;
                int sn = ok ? srcs[r] : 0;
                #pragma unroll
                for (int nf = 0; nf < NF; nf++) {
                    int cc = warpN + nf * 8 + ((lane & 3) << 1);
                    float v0 = 0.f, v1 = 0.f;
                    if (ok) {
                        v0 = acc[mf][nf][half * 2 + 0] + bias[cc];
                        v1 = acc[mf][nf][half * 2 + 1] + bias[cc + 1];
                        float at = __ldg(ATT + (size_t)r * 8 + (cc >> 4));
                        v0 = sigmoid_f(v0) * at * __ldg(V + (size_t)sn * 384 + cc);
                        v1 = sigmoid_f(v1) * at * __ldg(V + (size_t)sn * 384 + cc + 1);
                    }
                    tile[lr * TSTR + cc] = v0;
                    tile[lr * TSTR + cc + 1] = v1;
                }
            }
        }
        if (tid < 128) {
            int ge = row0 + tid;
            sdst[tid] = (ge < M) ? dsts[ge] : -1;
        }
        __syncthreads();
        int c = tid & 127, rbeg = (tid >> 7) * 64, rend = rbeg + 64;
        float accum = 0.f;
        int curd = sdst[rbeg];
        if (curd >= 0) {
            for (int r = rbeg; r < rend; r++) {
                int d = sdst[r];
                if (d < 0) break;
                if (d != curd) {
                    atomicAdd(&C[(size_t)curd * 128 + c], accum);
                    accum = 0.f;
                    curd = d;
                }
                accum += tile[r * TSTR + c];
            }
            atomicAdd(&C[(size_t)curd * 128 + c], accum);
        }
        return;
    }

    if (mode == 6) {
        // ---- HA tile + fused logits ----
        constexpr int TSTR = 72;                 // 288B rows: float4-aligned
        float* tile = dsm;                       // 128 x 72
        float* w2t = dsm + 128 * TSTR;           // [8][72] transposed w2
        float* b2s = w2t + 8 * TSTR;             // 8
        #pragma unroll
        for (int mf = 0; mf < 4; mf++) {
            #pragma unroll
            for (int half = 0; half < 2; half++) {
                int lr = warpM + mf * 16 + (lane >> 2) + half * 8;
                #pragma unroll
                for (int nf = 0; nf < NF; nf++) {
                    int cc = warpN + nf * 8 + ((lane & 3) << 1);
                    tile[lr * TSTR + cc] =
                        gelu_f(acc[mf][nf][half * 2 + 0] + bias[cc]);
                    tile[lr * TSTR + cc + 1] =
                        gelu_f(acc[mf][nf][half * 2 + 1] + bias[cc + 1]);
                }
            }
        }
        for (int i = tid; i < 512; i += 256) {
            int k = i >> 3, h = i & 7;
            w2t[h * TSTR + k] = gam[i];
        }
        if (tid < 8) b2s[tid] = bet[tid];
        __syncthreads();
        #pragma unroll
        for (int j = 0; j < 4; j++) {
            int p = tid + j * 256;
            int e = p >> 3, h = p & 7;
            int ge = row0 + e;
            if (ge >= M) continue;
            int dd = dsts[ge], sr = srcs[ge];
            const float* qp = V + (size_t)dd * 384 + h * 16;
            const float* kp = V + (size_t)sr * 384 + 128 + h * 16;
            float lg = 0.f;
            #pragma unroll
            for (int d = 0; d < 16; d += 4) {
                float4 qv = *(const float4*)(qp + d);
                float4 kv = *(const float4*)(kp + d);
                lg += qv.x * kv.x + qv.y * kv.y + qv.z * kv.z + qv.w * kv.w;
            }
            lg *= 0.25f;
            float a = b2s[h];
            const float* tr = tile + e * TSTR;
            const float* wr = w2t + h * TSTR;
            #pragma unroll
            for (int k = 0; k < 64; k += 4) {
                float4 tv = *(const float4*)(tr + k);
                float4 wv = *(const float4*)(wr + k);
                a += tv.x * wv.x + tv.y * wv.y + tv.z * wv.z + tv.w * wv.w;
            }
            C[(size_t)ge * 8 + h] = lg + a;
        }
        return;
    }

    // ---- normal epilogue ----
    #pragma unroll
    for (int mf = 0; mf < 4; mf++) {
        #pragma unroll
        for (int half = 0; half < 2; half++) {
            int r = row0 + warpM + mf * 16 + (lane >> 2) + half * 8;
            if (r >= M) continue;
            #pragma unroll
            for (int nf = 0; nf < NF; nf++) {
                int cc = col0 + warpN + nf * 8 + ((lane & 3) << 1);
                float v0 = acc[mf][nf][half * 2 + 0];
                float v1 = acc[mf][nf][half * 2 + 1];
                if (bias) { v0 += bias[cc]; v1 += bias[cc + 1]; }
                size_t idx = (size_t)r * N + cc;
                if (mode == 1) {
                    v0 = gelu_f(v0); v1 = gelu_f(v1);
                } else if (mode == 2) {
                    v0 += res[idx]; v1 += res[idx + 1];
                } else if (mode == 3) {
                    v0 = res[idx] + gam[idx] * v0 + bet[idx];
                    v1 = res[idx + 1] + gam[idx + 1] * v1 + bet[idx + 1];
                }
                *(float2*)(C + idx) = make_float2(v0, v1);
            }
        }
    }
}

// ---------------- pack Wq|Wk|Wv -> [128, 384] -------------------------------
__global__ void pack_wqkv(const float* __restrict__ Wq, const float* __restrict__ Wk,
                          const float* __restrict__ Wv, float* __restrict__ W) {
    int i = blockIdx.x * 256 + threadIdx.x;
    if (i >= 128 * 128) return;
    int k = i >> 7, j = i & 127;
    W[(size_t)k * 384 + j] = Wq[i];
    W[(size_t)k * 384 + 128 + j] = Wk[i];
    W[(size_t)k * 384 + 256 + j] = Wv[i];
}

// ---------------- LayerNorm -------------------------------------------------
__global__ void ln_kernel(const float* __restrict__ X, const float* __restrict__ G,
                          const float* __restrict__ B, float* __restrict__ O, int Nrows) {
    int warp = (blockIdx.x * blockDim.x + threadIdx.x) >> 5;
    int lane = threadIdx.x & 31;
    if (warp >= Nrows) return;
    const float* xp = X + (size_t)warp * 128;
    float4 v = *(const float4*)(xp + lane * 4);
    float s = v.x + v.y + v.z + v.w;
    #pragma unroll
    for (int o = 16; o; o >>= 1) s += __shfl_xor_sync(0xffffffffu, s, o);
    float mean = s * (1.0f / 128.0f);
    float d0 = v.x - mean, d1 = v.y - mean, d2 = v.z - mean, d3 = v.w - mean;
    float ss = d0 * d0 + d1 * d1 + d2 * d2 + d3 * d3;
    #pragma unroll
    for (int o = 16; o; o >>= 1) ss += __shfl_xor_sync(0xffffffffu, ss, o);
    float inv = rsqrtf(ss * (1.0f / 128.0f) + 1e-5f);
    float* op = O + (size_t)warp * 128;
    int c = lane * 4;
    op[c + 0] = d0 * inv * G[c + 0] + B[c + 0];
    op[c + 1] = d1 * inv * G[c + 1] + B[c + 1];
    op[c + 2] = d2 * inv * G[c + 2] + B[c + 2];
    op[c + 3] = d3 * inv * G[c + 3] + B[c + 3];
}

// ---------------- counting sort of edges by dst -----------------------------
__global__ void hist_kernel(const int* __restrict__ EI, int* __restrict__ cnt, int E) {
    int e = blockIdx.x * 256 + threadIdx.x;
    if (e < E) atomicAdd(&cnt[EI[E + e]], 1);
}
__global__ void scan1_kernel(const int* __restrict__ cnt, int* __restrict__ excl,
                             int* __restrict__ bsum, int N) {
    __shared__ int sm[256];
    int t = threadIdx.x, i = blockIdx.x * 256 + t;
    int v = (i < N) ? cnt[i] : 0;
    sm[t] = v; __syncthreads();
    for (int o = 1; o < 256; o <<= 1) {
        int a = (t >= o) ? sm[t - o] : 0;
        __syncthreads();
        sm[t] += a;
        __syncthreads();
    }
    if (i < N) excl[i] = sm[t] - v;
    if (t == 255) bsum[blockIdx.x] = sm[255];
}
__global__ void scan2_kernel(const int* __restrict__ bsum, int* __restrict__ bsumex, int nb) {
    __shared__ int sm[256];
    int t = threadIdx.x;
    int v = (t < nb) ? bsum[t] : 0;
    sm[t] = v; __syncthreads();
    for (int o = 1; o < 256; o <<= 1) {
        int a = (t >= o) ? sm[t - o] : 0;
        __syncthreads();
        sm[t] += a;
        __syncthreads();
    }
    bsumex[t] = sm[t] - v;
}
__global__ void scan3_kernel(int* __restrict__ rowstart, int* __restrict__ cursor,
                             const int* __restrict__ bsumex, int N, int E) {
    int i = blockIdx.x * 256 + threadIdx.x;
    if (i < N) {
        int v = rowstart[i] + bsumex[blockIdx.x];
        rowstart[i] = v;
        cursor[i] = v;
        if (i == N - 1) rowstart[N] = E;
    }
}
__global__ void scatter_kernel(const int* __restrict__ EI, int* __restrict__ cursor,
                               int* __restrict__ perm, int* __restrict__ srcs,
                               int* __restrict__ dsts, int E) {
    int e = blockIdx.x * 256 + threadIdx.x;
    if (e >= E) return;
    int d = EI[E + e];
    int pos = atomicAdd(&cursor[d], 1);
    perm[pos] = e;
    srcs[pos] = EI[e];
    dsts[pos] = d;
}

// ---------------- per-node softmax ------------------------------------------
__global__ void softmax_kernel(const float* __restrict__ LOG, const int* __restrict__ rowstart,
                               float* __restrict__ ATT, int N) {
    int warp = (blockIdx.x * blockDim.x + threadIdx.x) >> 5;
    int lane = threadIdx.x & 31;
    if (warp >= N) return;
    int s0 = rowstart[warp], s1 = rowstart[warp + 1];
    int eo = lane >> 3, h = lane & 7;
    float m = 0.0f;
    for (int i = s0 + eo; i < s1; i += 4) m = fmaxf(m, LOG[(size_t)i * 8 + h]);
    m = fmaxf(m, __shfl_xor_sync(0xffffffffu, m, 8));
    m = fmaxf(m, __shfl_xor_sync(0xffffffffu, m, 16));
    float s = 0.0f;
    for (int i = s0 + eo; i < s1; i += 4) s += expf(LOG[(size_t)i * 8 + h] - m);
    s += __shfl_xor_sync(0xffffffffu, s, 8);
    s += __shfl_xor_sync(0xffffffffu, s, 16);
    float inv = 1.0f / (s + 1e-10f);
    for (int i = s0 + eo; i < s1; i += 4)
        ATT[(size_t)i * 8 + h] = expf(LOG[(size_t)i * 8 + h] - m) * inv;
}

// ---------------- launch ----------------------------------------------------
extern "C" void kernel_launch(void* const* d_in, const int* in_sizes, int n_in,
                              void* d_out, int out_size) {
    const float* x      = (const float*)d_in[0];
    const float* ea     = (const float*)d_in[1];
    const float* gamma  = (const float*)d_in[2];
    const float* beta   = (const float*)d_in[3];
    const float* Wq     = (const float*)d_in[4];
    const float* Wk     = (const float*)d_in[5];
    const float* Wv     = (const float*)d_in[6];
    const float* Wo     = (const float*)d_in[7];
    const float* bo     = (const float*)d_in[8];
    const float* ea_w1  = (const float*)d_in[9];
    const float* ea_b1  = (const float*)d_in[10];
    const float* ea_w2  = (const float*)d_in[11];
    const float* ea_b2  = (const float*)d_in[12];
    const float* eg_w1  = (const float*)d_in[13];
    const float* eg_b1  = (const float*)d_in[14];
    const float* eg_w2  = (const float*)d_in[15];
    const float* eg_b2  = (const float*)d_in[16];
    const float* ln1_g  = (const float*)d_in[17];
    const float* ln1_b  = (const float*)d_in[18];
    const float* ln2_g  = (const float*)d_in[19];
    const float* ln2_b  = (const float*)d_in[20];
    const float* ffn_w1 = (const float*)d_in[21];
    const float* ffn_b1 = (const float*)d_in[22];
    const float* ffn_w2 = (const float*)d_in[23];
    const float* ffn_b2 = (const float*)d_in[24];
    const int*   ei     = (const int*)d_in[25];

    int N = in_sizes[0] / 128;
    int E = in_sizes[25] / 2;

    float *pXN, *pQKV, *pWQKV, *pAGG, *pXMID, *pFFNH, *pHE, *pLOG, *pATT;
    int *pPerm, *pSrc, *pDst, *pCnt, *pRow, *pCur, *pBsum, *pBsumex;
    cudaGetSymbolAddress((void**)&pXN, g_XN);
    cudaGetSymbolAddress((void**)&pQKV, g_QKV);
    cudaGetSymbolAddress((void**)&pWQKV, g_WQKV);
    cudaGetSymbolAddress((void**)&pAGG, g_AGG);
    cudaGetSymbolAddress((void**)&pXMID, g_XMID);
    cudaGetSymbolAddress((void**)&pFFNH, g_FFNH);
    cudaGetSymbolAddress((void**)&pHE, g_HE);
    cudaGetSymbolAddress((void**)&pLOG, g_LOG);
    cudaGetSymbolAddress((void**)&pATT, g_ATT);
    cudaGetSymbolAddress((void**)&pPerm, g_perm);
    cudaGetSymbolAddress((void**)&pSrc, g_srcs);
    cudaGetSymbolAddress((void**)&pDst, g_dsts);
    cudaGetSymbolAddress((void**)&pCnt, g_cnt);
    cudaGetSymbolAddress((void**)&pRow, g_rowstart);
    cudaGetSymbolAddress((void**)&pCur, g_cursor);
    cudaGetSymbolAddress((void**)&pBsum, g_bsum);
    cudaGetSymbolAddress((void**)&pBsumex, g_bsumex);

    const int smem128 = (2 * 128 * 36 + 2 * 32 * 132) * 4;   // 70656
    const int smem64  = (2 * 128 * 36 + 2 * 32 * 68) * 4;    // 54272
    cudaFuncSetAttribute(mma2<128>, cudaFuncAttributeMaxDynamicSharedMemorySize, smem128);
    cudaFuncSetAttribute(mma2<64>, cudaFuncAttributeMaxDynamicSharedMemorySize, smem64);

    int nb = (N + 255) / 256;
    int lnBlocks = (N * 32 + 255) / 256;
    dim3 gn(1, (N + 127) / 128);
    dim3 gqkv(3, (N + 127) / 128);
    dim3 ge(1, (E + 127) / 128);

    // order: memset,memset,pack,ln,QKV -> ncu -s 5 captures merged QKV GEMM
    cudaMemsetAsync(pCnt, 0, (size_t)N * sizeof(int));                       // 1
    cudaMemsetAsync(pAGG, 0, (size_t)N * 128 * sizeof(float));               // 2
    pack_wqkv<<<64, 256>>>(Wq, Wk, Wv, pWQKV);                               // 3
    ln_kernel<<<lnBlocks, 256>>>(x, ln1_g, ln1_b, pXN, N);                   // 4
    mma2<128><<<gqkv, 256, smem128>>>(pXN, pWQKV, nullptr, nullptr, nullptr, nullptr,
        nullptr, nullptr, nullptr, nullptr, pQKV, N, 384, 128, 0, nullptr);  // 5 <- profiled
    hist_kernel<<<(E + 255) / 256, 256>>>(ei, pCnt, E);
    scan1_kernel<<<nb, 256>>>(pCnt, pRow, pBsum, N);
    scan2_kernel<<<1, 256>>>(pBsum, pBsumex, nb);
    scan3_kernel<<<nb, 256>>>(pRow, pCur, pBsumex, N, E);
    scatter_kernel<<<(E + 255) / 256, 256>>>(ei, pCur, pPerm, pSrc, pDst, E);

    // LOG = QK/4 + gelu(EA[perm]@ea_w1+b1)@ea_w2 + b2   (mode 6)
    mma2<64><<<ge, 256, smem64>>>(ea, ea_w1, ea_b1, nullptr, ea_w2, ea_b2,
        pQKV, pSrc, pDst, nullptr, pLOG, E, 64, 32, 6, pPerm);
    softmax_kernel<<<(N * 32 + 255) / 256, 256>>>(pLOG, pRow, pATT, N);
    // HG = gelu(EA[perm] @ eg_w1 + b1)   [E, 64], K=32
    mma2<64><<<ge, 256, smem64>>>(ea, eg_w1, eg_b1, nullptr, nullptr, nullptr,
        nullptr, nullptr, nullptr, nullptr, pHE, E, 64, 32, 1, pPerm);
    // AGG += segreduce(sigmoid(HG @ eg_w2 + b2) * att * V[src])   mode 5
    mma2<128><<<ge, 256, smem128>>>(pHE, eg_w2, eg_b2, nullptr, nullptr, nullptr,
        pQKV + 256, pSrc, pDst, pATT, pAGG, E, 128, 64, 5, nullptr);

    mma2<128><<<gn, 256, smem128>>>(pAGG, Wo, bo, x, gamma, beta,
        nullptr, nullptr, nullptr, nullptr, pXMID, N, 128, 128, 3, nullptr);
    ln_kernel<<<lnBlocks, 256>>>(pXMID, ln2_g, ln2_b, pXN, N);
    dim3 gn2(2, (N + 127) / 128);
    mma2<128><<<gn2, 256, smem128>>>(pXN, ffn_w1, ffn_b1, nullptr, nullptr, nullptr,
        nullptr, nullptr, nullptr, nullptr, pFFNH, N, 256, 128, 1, nullptr);
    mma2<128><<<gn, 256, smem128>>>(pFFNH, ffn_w2, ffn_b2, pXMID, nullptr, nullptr,
        nullptr, nullptr, nullptr, nullptr, (float*)d_out, N, 128, 256, 2, nullptr);
}

// round 13
// speedup vs baseline: 1.2722x; 1.0331x over previous
#include <cuda_runtime.h>
#include <math.h>
#include <stdint.h>

#define NMAX 50000
#define EMAX 500000

// ---------------- static scratch ------------------------------------------
__device__ float g_XN[NMAX * 128];
__device__ float g_QKV[NMAX * 384];     // row-interleaved: Q | K | V per node
__device__ float g_WQKV[128 * 384];     // packed Wq|Wk|Wv
__device__ float g_W1P[32 * 128];       // packed ea_w1|eg_w1
__device__ float g_B1P[128];            // packed ea_b1|eg_b1
__device__ float g_AGG[NMAX * 128];
__device__ float g_XMID[NMAX * 128];
__device__ float g_FFNH[NMAX * 256];
__device__ float g_HE[EMAX * 64];
__device__ float g_LOG[EMAX * 8];
__device__ float g_ATT[EMAX * 8];
__device__ int   g_perm[EMAX];
__device__ int   g_srcs[EMAX];
__device__ int   g_dsts[EMAX];
__device__ int   g_cnt[NMAX];
__device__ int   g_rowstart[NMAX + 1];
__device__ int   g_cursor[NMAX];
__device__ int   g_bsum[256];
__device__ int   g_bsumex[256];

__device__ __forceinline__ float gelu_f(float x) {
    return 0.5f * x * (1.0f + erff(x * 0.70710678118654752f));
}
__device__ __forceinline__ float sigmoid_f(float x) {
    return 1.0f / (1.0f + expf(-x));
}

__device__ __forceinline__ void cpa16(uint32_t dst, const void* src, bool valid) {
    int sz = valid ? 16 : 0;
    asm volatile("cp.async.cg.shared.global [%0], [%1], 16, %2;"
                 :: "r"(dst), "l"(src), "r"(sz) : "memory");
}
#define CP_COMMIT() asm volatile("cp.async.commit_group;" ::: "memory")
template <int Ng>
__device__ __forceinline__ void cp_wait() {
    asm volatile("cp.async.wait_group %0;" :: "n"(Ng) : "memory");
}

__device__ __forceinline__ void mma_tf32(float* c, const unsigned* a, const unsigned* b) {
    asm volatile(
        "mma.sync.aligned.m16n8k8.row.col.f32.tf32.tf32.f32 "
        "{%0,%1,%2,%3}, {%4,%5,%6,%7}, {%8,%9}, {%0,%1,%2,%3};"
        : "+f"(c[0]), "+f"(c[1]), "+f"(c[2]), "+f"(c[3])
        : "r"(a[0]), "r"(a[1]), "r"(a[2]), "r"(a[3]), "r"(b[0]), "r"(b[1]));
}
__device__ __forceinline__ void ldsm_x4(unsigned* a, uint32_t addr) {
    asm volatile("ldmatrix.sync.aligned.m8n8.x4.shared.b16 {%0,%1,%2,%3}, [%4];"
                 : "=r"(a[0]), "=r"(a[1]), "=r"(a[2]), "=r"(a[3]) : "r"(addr));
}

// ---------------- tf32 mma GEMM: 2-stage cp.async + ldmatrix A --------------
// 128 rows x 128 cols per CTA, BK=32, 8 warps.
// modes: 0:+bias 1:gelu 2:res+ 3:res+gam*+bet
//   5: gate+reduce: v=sigmoid(+bias)*ATT*V[srcs[row]] (V = QKV V-section,
//      stride 384); dst-sorted rows segment-reduced into C via atomics.
//   7: combined edge hidden: cols 0-63 HA -> gelu -> smem tile -> fused
//      logits C[e,h]=Q[dst].K[src]/4 + HA.w2[:,h] + b2[h]; cols 64-127
//      HG -> gelu -> C2[e,0..63].  (gam=w2 [64,8], bet=b2, V=QKV base)
__global__ void __launch_bounds__(256, 2) mma2(
        const float* __restrict__ A, const float* __restrict__ W,
        const float* __restrict__ bias, const float* __restrict__ res,
        const float* __restrict__ gam, const float* __restrict__ bet,
        const float* __restrict__ V, const int* __restrict__ srcs,
        const int* __restrict__ dsts, const float* __restrict__ ATT,
        float* __restrict__ C, float* __restrict__ C2,
        int M, int N, int K, int mode, const int* __restrict__ rowidx) {
    constexpr int BN = 128;
    constexpr int NF = 4;
    constexpr int WN = 32;
    constexpr int ASTR = 36;
    constexpr int BSTR = BN + 4;
    constexpr int ASZ = 128 * ASTR;
    constexpr int BSZ = 32 * BSTR;
    extern __shared__ float dsm[];
    float* Abuf = dsm;
    float* Bbuf = dsm + 2 * ASZ;
    const uint32_t aAddr = (uint32_t)__cvta_generic_to_shared(Abuf);
    const uint32_t bAddr = (uint32_t)__cvta_generic_to_shared(Bbuf);
    const int tid = threadIdx.x, lane = tid & 31, wid = tid >> 5;
    const int wm = wid & 1, wn = wid >> 1;
    const int row0 = blockIdx.y * 128, col0 = blockIdx.x * BN;
    const int warpM = wm * 64, warpN = wn * WN;
    const int g = lane >> 3, rl = lane & 7;
    const uint32_t aLaneOff = (uint32_t)(((rl + (g & 1) * 8) * ASTR + (g >> 1) * 4) * 4);
    float acc[4][NF][4];
    #pragma unroll
    for (int i = 0; i < 4; i++)
        #pragma unroll
        for (int j = 0; j < NF; j++) {
            acc[i][j][0] = 0.f; acc[i][j][1] = 0.f; acc[i][j][2] = 0.f; acc[i][j][3] = 0.f;
        }

    const int ntiles = K >> 5;

    auto load_tile = [&](int stage, int t) {
        const int kt = t << 5;
        uint32_t ab = aAddr + stage * (ASZ * 4);
        #pragma unroll
        for (int it = 0; it < 4; it++) {
            int cI = tid + it * 256;
            int r = cI >> 3, q = cI & 7;
            int gr = row0 + r;
            bool v = gr < M;
            const float* src = A;
            if (v) {
                int pr = rowidx ? rowidx[gr] : gr;
                src = A + (size_t)pr * K + kt + q * 4;
            }
            cpa16(ab + (uint32_t)(r * ASTR + q * 4) * 4, src, v);
        }
        uint32_t bb = bAddr + stage * (BSZ * 4);
        #pragma unroll
        for (int it = 0; it < 4; it++) {
            int cI = tid + it * 256;
            int kr = cI >> 5, q = cI & 31;
            cpa16(bb + (uint32_t)(kr * BSTR + q * 4) * 4,
                  W + (size_t)(kt + kr) * N + col0 + q * 4, true);
        }
    };

    load_tile(0, 0);
    CP_COMMIT();
    for (int t = 0; t < ntiles; t++) {
        int cur = t & 1;
        if (t + 1 < ntiles) {
            load_tile(1 - cur, t + 1);
            CP_COMMIT();
            cp_wait<1>();
        } else {
            cp_wait<0>();
        }
        __syncthreads();
        const uint32_t aWarp = aAddr + (uint32_t)(cur * ASZ) * 4 +
                               (uint32_t)(warpM * ASTR) * 4 + aLaneOff;
        const float* Bb = Bbuf + cur * BSZ;
        #pragma unroll
        for (int ks = 0; ks < 4; ks++) {
            int k = ks * 8 + (lane & 3);
            unsigned af[4][4];
            #pragma unroll
            for (int mf = 0; mf < 4; mf++)
                ldsm_x4(af[mf], aWarp + (uint32_t)(mf * 16 * ASTR * 4 + ks * 32));
            unsigned bf[NF][2];
            #pragma unroll
            for (int nf = 0; nf < NF; nf++) {
                int n0 = warpN + nf * 8 + (lane >> 2);
                bf[nf][0] = __float_as_uint(Bb[k * BSTR + n0]);
                bf[nf][1] = __float_as_uint(Bb[(k + 4) * BSTR + n0]);
            }
            #pragma unroll
            for (int mf = 0; mf < 4; mf++)
                #pragma unroll
                for (int nf = 0; nf < NF; nf++)
                    mma_tf32(acc[mf][nf], af[mf], bf[nf]);
        }
        __syncthreads();
    }

    if (mode == 5) {
        // ---- fused gate epilogue + per-dst segment reduction ----
        constexpr int TSTR = 132;
        float* tile = dsm;
        int* sdst = (int*)(dsm + 128 * TSTR);
        #pragma unroll
        for (int mf = 0; mf < 4; mf++) {
            #pragma unroll
            for (int half = 0; half < 2; half++) {
                int lr = warpM + mf * 16 + (lane >> 2) + half * 8;
                int r = row0 + lr;
                bool ok = r < M;
                int sn = ok ? srcs[r] : 0;
                #pragma unroll
                for (int nf = 0; nf < NF; nf++) {
                    int cc = warpN + nf * 8 + ((lane & 3) << 1);
                    float v0 = 0.f, v1 = 0.f;
                    if (ok) {
                        v0 = acc[mf][nf][half * 2 + 0] + bias[cc];
                        v1 = acc[mf][nf][half * 2 + 1] + bias[cc + 1];
                        float at = __ldg(ATT + (size_t)r * 8 + (cc >> 4));
                        v0 = sigmoid_f(v0) * at * __ldg(V + (size_t)sn * 384 + cc);
                        v1 = sigmoid_f(v1) * at * __ldg(V + (size_t)sn * 384 + cc + 1);
                    }
                    tile[lr * TSTR + cc] = v0;
                    tile[lr * TSTR + cc + 1] = v1;
                }
            }
        }
        if (tid < 128) {
            int ge = row0 + tid;
            sdst[tid] = (ge < M) ? dsts[ge] : -1;
        }
        __syncthreads();
        int c = tid & 127, rbeg = (tid >> 7) * 64, rend = rbeg + 64;
        float accum = 0.f;
        int curd = sdst[rbeg];
        if (curd >= 0) {
            for (int r = rbeg; r < rend; r++) {
                int d = sdst[r];
                if (d < 0) break;
                if (d != curd) {
                    atomicAdd(&C[(size_t)curd * 128 + c], accum);
                    accum = 0.f;
                    curd = d;
                }
                accum += tile[r * TSTR + c];
            }
            atomicAdd(&C[(size_t)curd * 128 + c], accum);
        }
        return;
    }

    if (mode == 7) {
        // ---- combined edge hidden: HA (cols 0-63) + HG (cols 64-127) ----
        constexpr int TSTR = 72;
        float* tile = dsm;                       // 128 x 72 (HA)
        float* w2t = dsm + 128 * TSTR;           // [8][72] transposed w2
        float* b2s = w2t + 8 * TSTR;             // 8
        #pragma unroll
        for (int mf = 0; mf < 4; mf++) {
            #pragma unroll
            for (int half = 0; half < 2; half++) {
                int lr = warpM + mf * 16 + (lane >> 2) + half * 8;
                int r = row0 + lr;
                bool ok = r < M;
                #pragma unroll
                for (int nf = 0; nf < NF; nf++) {
                    int cc = warpN + nf * 8 + ((lane & 3) << 1);
                    float v0 = gelu_f(acc[mf][nf][half * 2 + 0] + bias[cc]);
                    float v1 = gelu_f(acc[mf][nf][half * 2 + 1] + bias[cc + 1]);
                    if (cc < 64) {
                        tile[lr * TSTR + cc] = v0;
                        tile[lr * TSTR + cc + 1] = v1;
                    } else if (ok) {
                        *(float2*)(C2 + (size_t)r * 64 + (cc - 64)) = make_float2(v0, v1);
                    }
                }
            }
        }
        for (int i = tid; i < 512; i += 256) {
            int k = i >> 3, h = i & 7;
            w2t[h * TSTR + k] = gam[i];
        }
        if (tid < 8) b2s[tid] = bet[tid];
        __syncthreads();
        #pragma unroll
        for (int j = 0; j < 4; j++) {
            int p = tid + j * 256;
            int e = p >> 3, h = p & 7;
            int ge = row0 + e;
            if (ge >= M) continue;
            int dd = dsts[ge], sr = srcs[ge];
            const float* qp = V + (size_t)dd * 384 + h * 16;
            const float* kp = V + (size_t)sr * 384 + 128 + h * 16;
            float lg = 0.f;
            #pragma unroll
            for (int d = 0; d < 16; d += 4) {
                float4 qv = *(const float4*)(qp + d);
                float4 kv = *(const float4*)(kp + d);
                lg += qv.x * kv.x + qv.y * kv.y + qv.z * kv.z + qv.w * kv.w;
            }
            lg *= 0.25f;
            float a = b2s[h];
            const float* tr = tile + e * TSTR;
            const float* wr = w2t + h * TSTR;
            #pragma unroll
            for (int k = 0; k < 64; k += 4) {
                float4 tv = *(const float4*)(tr + k);
                float4 wv = *(const float4*)(wr + k);
                a += tv.x * wv.x + tv.y * wv.y + tv.z * wv.z + tv.w * wv.w;
            }
            C[(size_t)ge * 8 + h] = lg + a;
        }
        return;
    }

    // ---- normal epilogue ----
    #pragma unroll
    for (int mf = 0; mf < 4; mf++) {
        #pragma unroll
        for (int half = 0; half < 2; half++) {
            int r = row0 + warpM + mf * 16 + (lane >> 2) + half * 8;
            if (r >= M) continue;
            #pragma unroll
            for (int nf = 0; nf < NF; nf++) {
                int cc = col0 + warpN + nf * 8 + ((lane & 3) << 1);
                float v0 = acc[mf][nf][half * 2 + 0];
                float v1 = acc[mf][nf][half * 2 + 1];
                if (bias) { v0 += bias[cc]; v1 += bias[cc + 1]; }
                size_t idx = (size_t)r * N + cc;
                if (mode == 1) {
                    v0 = gelu_f(v0); v1 = gelu_f(v1);
                } else if (mode == 2) {
                    v0 += res[idx]; v1 += res[idx + 1];
                } else if (mode == 3) {
                    v0 = res[idx] + gam[idx] * v0 + bet[idx];
                    v1 = res[idx + 1] + gam[idx + 1] * v1 + bet[idx + 1];
                }
                *(float2*)(C + idx) = make_float2(v0, v1);
            }
        }
    }
}

// ---------------- pack kernels ----------------------------------------------
__global__ void pack_wqkv(const float* __restrict__ Wq, const float* __restrict__ Wk,
                          const float* __restrict__ Wv, float* __restrict__ W) {
    int i = blockIdx.x * 256 + threadIdx.x;
    if (i >= 128 * 128) return;
    int k = i >> 7, j = i & 127;
    W[(size_t)k * 384 + j] = Wq[i];
    W[(size_t)k * 384 + 128 + j] = Wk[i];
    W[(size_t)k * 384 + 256 + j] = Wv[i];
}
__global__ void pack_w1(const float* __restrict__ Wa, const float* __restrict__ Wg,
                        const float* __restrict__ Ba, const float* __restrict__ Bg,
                        float* __restrict__ W, float* __restrict__ B) {
    int i = blockIdx.x * 256 + threadIdx.x;
    if (i < 32 * 64) {
        int k = i >> 6, j = i & 63;
        W[(size_t)k * 128 + j] = Wa[i];
        W[(size_t)k * 128 + 64 + j] = Wg[i];
    }
    if (i < 64) {
        B[i] = Ba[i];
        B[64 + i] = Bg[i];
    }
}

// ---------------- LayerNorm -------------------------------------------------
__global__ void ln_kernel(const float* __restrict__ X, const float* __restrict__ G,
                          const float* __restrict__ B, float* __restrict__ O, int Nrows) {
    int warp = (blockIdx.x * blockDim.x + threadIdx.x) >> 5;
    int lane = threadIdx.x & 31;
    if (warp >= Nrows) return;
    const float* xp = X + (size_t)warp * 128;
    float4 v = *(const float4*)(xp + lane * 4);
    float s = v.x + v.y + v.z + v.w;
    #pragma unroll
    for (int o = 16; o; o >>= 1) s += __shfl_xor_sync(0xffffffffu, s, o);
    float mean = s * (1.0f / 128.0f);
    float d0 = v.x - mean, d1 = v.y - mean, d2 = v.z - mean, d3 = v.w - mean;
    float ss = d0 * d0 + d1 * d1 + d2 * d2 + d3 * d3;
    #pragma unroll
    for (int o = 16; o; o >>= 1) ss += __shfl_xor_sync(0xffffffffu, ss, o);
    float inv = rsqrtf(ss * (1.0f / 128.0f) + 1e-5f);
    float* op = O + (size_t)warp * 128;
    int c = lane * 4;
    op[c + 0] = d0 * inv * G[c + 0] + B[c + 0];
    op[c + 1] = d1 * inv * G[c + 1] + B[c + 1];
    op[c + 2] = d2 * inv * G[c + 2] + B[c + 2];
    op[c + 3] = d3 * inv * G[c + 3] + B[c + 3];
}

// ---------------- counting sort of edges by dst -----------------------------
__global__ void hist_kernel(const int* __restrict__ EI, int* __restrict__ cnt, int E) {
    int e = blockIdx.x * 256 + threadIdx.x;
    if (e < E) atomicAdd(&cnt[EI[E + e]], 1);
}
__global__ void scan1_kernel(const int* __restrict__ cnt, int* __restrict__ excl,
                             int* __restrict__ bsum, int N) {
    __shared__ int sm[256];
    int t = threadIdx.x, i = blockIdx.x * 256 + t;
    int v = (i < N) ? cnt[i] : 0;
    sm[t] = v; __syncthreads();
    for (int o = 1; o < 256; o <<= 1) {
        int a = (t >= o) ? sm[t - o] : 0;
        __syncthreads();
        sm[t] += a;
        __syncthreads();
    }
    if (i < N) excl[i] = sm[t] - v;
    if (t == 255) bsum[blockIdx.x] = sm[255];
}
__global__ void scan2_kernel(const int* __restrict__ bsum, int* __restrict__ bsumex, int nb) {
    __shared__ int sm[256];
    int t = threadIdx.x;
    int v = (t < nb) ? bsum[t] : 0;
    sm[t] = v; __syncthreads();
    for (int o = 1; o < 256; o <<= 1) {
        int a = (t >= o) ? sm[t - o] : 0;
        __syncthreads();
        sm[t] += a;
        __syncthreads();
    }
    bsumex[t] = sm[t] - v;
}
__global__ void scan3_kernel(int* __restrict__ rowstart, int* __restrict__ cursor,
                             const int* __restrict__ bsumex, int N, int E) {
    int i = blockIdx.x * 256 + threadIdx.x;
    if (i < N) {
        int v = rowstart[i] + bsumex[blockIdx.x];
        rowstart[i] = v;
        cursor[i] = v;
        if (i == N - 1) rowstart[N] = E;
    }
}
__global__ void scatter_kernel(const int* __restrict__ EI, int* __restrict__ cursor,
                               int* __restrict__ perm, int* __restrict__ srcs,
                               int* __restrict__ dsts, int E) {
    int e = blockIdx.x * 256 + threadIdx.x;
    if (e >= E) return;
    int d = EI[E + e];
    int pos = atomicAdd(&cursor[d], 1);
    perm[pos] = e;
    srcs[pos] = EI[e];
    dsts[pos] = d;
}

// ---------------- per-node softmax ------------------------------------------
__global__ void softmax_kernel(const float* __restrict__ LOG, const int* __restrict__ rowstart,
                               float* __restrict__ ATT, int N) {
    int warp = (blockIdx.x * blockDim.x + threadIdx.x) >> 5;
    int lane = threadIdx.x & 31;
    if (warp >= N) return;
    int s0 = rowstart[warp], s1 = rowstart[warp + 1];
    int eo = lane >> 3, h = lane & 7;
    float m = 0.0f;
    for (int i = s0 + eo; i < s1; i += 4) m = fmaxf(m, LOG[(size_t)i * 8 + h]);
    m = fmaxf(m, __shfl_xor_sync(0xffffffffu, m, 8));
    m = fmaxf(m, __shfl_xor_sync(0xffffffffu, m, 16));
    float s = 0.0f;
    for (int i = s0 + eo; i < s1; i += 4) s += expf(LOG[(size_t)i * 8 + h] - m);
    s += __shfl_xor_sync(0xffffffffu, s, 8);
    s += __shfl_xor_sync(0xffffffffu, s, 16);
    float inv = 1.0f / (s + 1e-10f);
    for (int i = s0 + eo; i < s1; i += 4)
        ATT[(size_t)i * 8 + h] = expf(LOG[(size_t)i * 8 + h] - m) * inv;
}

// ---------------- launch ----------------------------------------------------
extern "C" void kernel_launch(void* const* d_in, const int* in_sizes, int n_in,
                              void* d_out, int out_size) {
    const float* x      = (const float*)d_in[0];
    const float* ea     = (const float*)d_in[1];
    const float* gamma  = (const float*)d_in[2];
    const float* beta   = (const float*)d_in[3];
    const float* Wq     = (const float*)d_in[4];
    const float* Wk     = (const float*)d_in[5];
    const float* Wv     = (const float*)d_in[6];
    const float* Wo     = (const float*)d_in[7];
    const float* bo     = (const float*)d_in[8];
    const float* ea_w1  = (const float*)d_in[9];
    const float* ea_b1  = (const float*)d_in[10];
    const float* ea_w2  = (const float*)d_in[11];
    const float* ea_b2  = (const float*)d_in[12];
    const float* eg_w1  = (const float*)d_in[13];
    const float* eg_b1  = (const float*)d_in[14];
    const float* eg_w2  = (const float*)d_in[15];
    const float* eg_b2  = (const float*)d_in[16];
    const float* ln1_g  = (const float*)d_in[17];
    const float* ln1_b  = (const float*)d_in[18];
    const float* ln2_g  = (const float*)d_in[19];
    const float* ln2_b  = (const float*)d_in[20];
    const float* ffn_w1 = (const float*)d_in[21];
    const float* ffn_b1 = (const float*)d_in[22];
    const float* ffn_w2 = (const float*)d_in[23];
    const float* ffn_b2 = (const float*)d_in[24];
    const int*   ei     = (const int*)d_in[25];

    int N = in_sizes[0] / 128;
    int E = in_sizes[25] / 2;

    float *pXN, *pQKV, *pWQKV, *pW1P, *pB1P, *pAGG, *pXMID, *pFFNH, *pHE, *pLOG, *pATT;
    int *pPerm, *pSrc, *pDst, *pCnt, *pRow, *pCur, *pBsum, *pBsumex;
    cudaGetSymbolAddress((void**)&pXN, g_XN);
    cudaGetSymbolAddress((void**)&pQKV, g_QKV);
    cudaGetSymbolAddress((void**)&pWQKV, g_WQKV);
    cudaGetSymbolAddress((void**)&pW1P, g_W1P);
    cudaGetSymbolAddress((void**)&pB1P, g_B1P);
    cudaGetSymbolAddress((void**)&pAGG, g_AGG);
    cudaGetSymbolAddress((void**)&pXMID, g_XMID);
    cudaGetSymbolAddress((void**)&pFFNH, g_FFNH);
    cudaGetSymbolAddress((void**)&pHE, g_HE);
    cudaGetSymbolAddress((void**)&pLOG, g_LOG);
    cudaGetSymbolAddress((void**)&pATT, g_ATT);
    cudaGetSymbolAddress((void**)&pPerm, g_perm);
    cudaGetSymbolAddress((void**)&pSrc, g_srcs);
    cudaGetSymbolAddress((void**)&pDst, g_dsts);
    cudaGetSymbolAddress((void**)&pCnt, g_cnt);
    cudaGetSymbolAddress((void**)&pRow, g_rowstart);
    cudaGetSymbolAddress((void**)&pCur, g_cursor);
    cudaGetSymbolAddress((void**)&pBsum, g_bsum);
    cudaGetSymbolAddress((void**)&pBsumex, g_bsumex);

    const int smem128 = (2 * 128 * 36 + 2 * 32 * 132) * 4;   // 70656
    cudaFuncSetAttribute(mma2, cudaFuncAttributeMaxDynamicSharedMemorySize, smem128);

    int nb = (N + 255) / 256;
    int lnBlocks = (N * 32 + 255) / 256;
    dim3 gn(1, (N + 127) / 128);
    dim3 gqkv(3, (N + 127) / 128);
    dim3 ge(1, (E + 127) / 128);

    // order: memset,memset,pack,ln,QKV -> ncu -s 5 captures merged QKV GEMM
    cudaMemsetAsync(pCnt, 0, (size_t)N * sizeof(int));                       // 1
    cudaMemsetAsync(pAGG, 0, (size_t)N * 128 * sizeof(float));               // 2
    pack_wqkv<<<64, 256>>>(Wq, Wk, Wv, pWQKV);                               // 3
    ln_kernel<<<lnBlocks, 256>>>(x, ln1_g, ln1_b, pXN, N);                   // 4
    mma2<<<gqkv, 256, smem128>>>(pXN, pWQKV, nullptr, nullptr, nullptr, nullptr,
        nullptr, nullptr, nullptr, nullptr, pQKV, nullptr, N, 384, 128, 0, nullptr); // 5
    pack_w1<<<8, 256>>>(ea_w1, eg_w1, ea_b1, eg_b1, pW1P, pB1P);
    hist_kernel<<<(E + 255) / 256, 256>>>(ei, pCnt, E);
    scan1_kernel<<<nb, 256>>>(pCnt, pRow, pBsum, N);
    scan2_kernel<<<1, 256>>>(pBsum, pBsumex, nb);
    scan3_kernel<<<nb, 256>>>(pRow, pCur, pBsumex, N, E);
    scatter_kernel<<<(E + 255) / 256, 256>>>(ei, pCur, pPerm, pSrc, pDst, E);

    // combined edge hidden (mode 7): LOG + HE in one pass over gathered EA
    mma2<<<ge, 256, smem128>>>(ea, pW1P, pB1P, nullptr, ea_w2, ea_b2,
        pQKV, pSrc, pDst, nullptr, pLOG, pHE, E, 128, 32, 7, pPerm);
    softmax_kernel<<<(N * 32 + 255) / 256, 256>>>(pLOG, pRow, pATT, N);
    // AGG += segreduce(sigmoid(HE @ eg_w2 + b2) * att * V[src])   mode 5
    mma2<<<ge, 256, smem128>>>(pHE, eg_w2, eg_b2, nullptr, nullptr, nullptr,
        pQKV + 256, pSrc, pDst, pATT, pAGG, nullptr, E, 128, 64, 5, nullptr);

    mma2<<<gn, 256, smem128>>>(pAGG, Wo, bo, x, gamma, beta,
        nullptr, nullptr, nullptr, nullptr, pXMID, nullptr, N, 128, 128, 3, nullptr);
    ln_kernel<<<lnBlocks, 256>>>(pXMID, ln2_g, ln2_b, pXN, N);
    dim3 gn2(2, (N + 127) / 128);
    mma2<<<gn2, 256, smem128>>>(pXN, ffn_w1, ffn_b1, nullptr, nullptr, nullptr,
        nullptr, nullptr, nullptr, nullptr, pFFNH, nullptr, N, 256, 128, 1, nullptr);
    mma2<<<gn, 256, smem128>>>(pFFNH, ffn_w2, ffn_b2, pXMID, nullptr, nullptr,
        nullptr, nullptr, nullptr, nullptr, (float*)d_out, nullptr, N, 128, 256, 2, nullptr);
}